// round 1
// baseline (speedup 1.0000x reference)
#include <cuda_runtime.h>
#include <math.h>

#define BB 4
#define CC 256
#define NN 4096          // H*W
#define MT (BB*NN)       // 16384 total tokens

// ---------------- scratch (device globals — no allocation) ----------------
static __device__ float g_X[(size_t)BB*NN*CC];   // X + PE, (B,N,C)
static __device__ float g_Q[(size_t)BB*NN*CC];
static __device__ float g_K[(size_t)BB*NN*CC];
static __device__ float g_V[(size_t)BB*NN*CC];
static __device__ float g_Y[(size_t)BB*NN*CC];
static __device__ float g_S[(size_t)BB*NN*NN];   // 256 MB attention matrix

// ---------------- kernel 1: x + PE, transpose (B,C,H,W)->(B,N,C) ----------
__global__ void pe_transpose_kernel(const float* __restrict__ x) {
    __shared__ float tile[32][33];
    int b  = blockIdx.z;
    int c0 = blockIdx.y * 32, n0 = blockIdx.x * 32;
    int tx = threadIdx.x, ty = threadIdx.y;
    tile[ty][tx] = x[((size_t)(b*CC + c0 + ty))*NN + n0 + tx];
    __syncthreads();
    int c = c0 + tx, n = n0 + ty;
    int h = n >> 6, w = n & 63;
    int pos, cc;
    if (c < 128) { pos = w; cc = c; } else { pos = h; cc = c - 128; }
    int j = cc & 63;                       // sin uses cc<64, cos uses cc-64
    // inv = 10000^(-j/64) = exp(-j * ln(1e4)/64)
    float inv = expf(-0.14391156831212787f * (float)j);
    float arg = (float)pos * inv;
    float pe = (cc >= 64) ? cosf(arg) : sinf(arg);
    g_X[((size_t)(b*NN + n))*CC + c] = tile[tx][ty] + pe;
}

// ---------------- tiled fp32 GEMM ------------------------------------------
// TB=true : C[m][n] = alpha * sum_k A[m][k] * B[n][k]   (B row-major, NT)
// TB=false: C[m][n] = alpha * sum_k A[m][k] * B[k][n]   (B row-major, NN)
template<bool TB>
__global__ __launch_bounds__(256)
void sgemm_kernel(const float* __restrict__ A, const float* __restrict__ Bm,
                  float* __restrict__ Cm, int M, int Nn, int K, float alpha,
                  long long sA, long long sB, long long sC)
{
    A  += (long long)blockIdx.z * sA;
    Bm += (long long)blockIdx.z * sB;
    Cm += (long long)blockIdx.z * sC;

    __shared__ __align__(16) float As[16][64];
    __shared__ __align__(16) float Bs[16][64];

    int tx = threadIdx.x, ty = threadIdx.y;
    int tid = ty * 16 + tx;
    int rowBase = blockIdx.y * 64, colBase = blockIdx.x * 64;

    int lm = tid >> 2;            // 0..63
    int lk = (tid & 3) * 4;       // 0,4,8,12
    int bk = tid >> 4;            // 0..15
    int bn = (tid & 15) * 4;      // 0..60

    float acc[4][4] = {};

    for (int kt = 0; kt < K; kt += 16) {
        // A tile: As[k][m] = A[rowBase+m][kt+k]
        float4 a4 = *(const float4*)(A + (size_t)(rowBase + lm) * K + kt + lk);
        As[lk+0][lm] = a4.x; As[lk+1][lm] = a4.y;
        As[lk+2][lm] = a4.z; As[lk+3][lm] = a4.w;
        if (TB) {
            float4 b4 = *(const float4*)(Bm + (size_t)(colBase + lm) * K + kt + lk);
            Bs[lk+0][lm] = b4.x; Bs[lk+1][lm] = b4.y;
            Bs[lk+2][lm] = b4.z; Bs[lk+3][lm] = b4.w;
        } else {
            float4 b4 = *(const float4*)(Bm + (size_t)(kt + bk) * Nn + colBase + bn);
            *(float4*)&Bs[bk][bn] = b4;
        }
        __syncthreads();
        #pragma unroll
        for (int kk = 0; kk < 16; kk++) {
            float4 av = *(const float4*)&As[kk][ty * 4];
            float4 bv = *(const float4*)&Bs[kk][tx * 4];
            float a[4] = {av.x, av.y, av.z, av.w};
            float b[4] = {bv.x, bv.y, bv.z, bv.w};
            #pragma unroll
            for (int i = 0; i < 4; i++)
                #pragma unroll
                for (int j = 0; j < 4; j++)
                    acc[i][j] += a[i] * b[j];
        }
        __syncthreads();
    }

    #pragma unroll
    for (int i = 0; i < 4; i++) {
        float4 o = make_float4(acc[i][0]*alpha, acc[i][1]*alpha,
                               acc[i][2]*alpha, acc[i][3]*alpha);
        *(float4*)(Cm + (size_t)(rowBase + ty*4 + i) * Nn + colBase + tx*4) = o;
    }
}

// ---------------- kernel: row softmax over g_S (rows of 4096) -------------
__global__ __launch_bounds__(256)
void softmax_kernel() {
    size_t row = blockIdx.x;
    float* p = g_S + row * (size_t)NN;
    int t = threadIdx.x;
    float v[16];
    float mx = -INFINITY;
    #pragma unroll
    for (int i = 0; i < 16; i++) { v[i] = p[t + i*256]; mx = fmaxf(mx, v[i]); }

    __shared__ float red[256];
    red[t] = mx; __syncthreads();
    for (int s = 128; s > 0; s >>= 1) {
        if (t < s) red[t] = fmaxf(red[t], red[t + s]);
        __syncthreads();
    }
    mx = red[0]; __syncthreads();

    float sum = 0.f;
    #pragma unroll
    for (int i = 0; i < 16; i++) { v[i] = expf(v[i] - mx); sum += v[i]; }
    red[t] = sum; __syncthreads();
    for (int s = 128; s > 0; s >>= 1) {
        if (t < s) red[t] += red[t + s];
        __syncthreads();
    }
    float inv = 1.0f / red[0];
    #pragma unroll
    for (int i = 0; i < 16; i++) p[t + i*256] = v[i] * inv;
}

// ---------------- kernel: Y (B,N,C) -> out (B,C,H,W) ----------------------
__global__ void out_transpose_kernel(float* __restrict__ out) {
    __shared__ float tile[32][33];
    int b  = blockIdx.z;
    int c0 = blockIdx.y * 32, n0 = blockIdx.x * 32;
    int tx = threadIdx.x, ty = threadIdx.y;
    tile[ty][tx] = g_Y[((size_t)(b*NN + n0 + ty))*CC + c0 + tx];
    __syncthreads();
    out[((size_t)(b*CC + c0 + ty))*NN + n0 + tx] = tile[tx][ty];
}

// ---------------- launch ----------------------------------------------------
extern "C" void kernel_launch(void* const* d_in, const int* in_sizes, int n_in,
                              void* d_out, int out_size)
{
    const float* x  = (const float*)d_in[0];
    const float* wq = (const float*)d_in[1];
    const float* wk = (const float*)d_in[2];
    const float* wv = (const float*)d_in[3];
    float* out = (float*)d_out;

    float *X, *Q, *K, *V, *S, *Y;
    cudaGetSymbolAddress((void**)&X, g_X);
    cudaGetSymbolAddress((void**)&Q, g_Q);
    cudaGetSymbolAddress((void**)&K, g_K);
    cudaGetSymbolAddress((void**)&V, g_V);
    cudaGetSymbolAddress((void**)&S, g_S);
    cudaGetSymbolAddress((void**)&Y, g_Y);

    dim3 b32(32, 32);
    dim3 bg(16, 16);

    // 1) X = x + PE, transposed to (B,N,C)
    pe_transpose_kernel<<<dim3(NN/32, CC/32, BB), b32>>>(x);

    // 2) Q/K/V = X @ W^T  (M=16384, N=256, K=256)
    sgemm_kernel<true><<<dim3(CC/64, MT/64, 1), bg>>>(X, wq, Q, MT, CC, CC, 1.0f, 0, 0, 0);
    sgemm_kernel<true><<<dim3(CC/64, MT/64, 1), bg>>>(X, wk, K, MT, CC, CC, 1.0f, 0, 0, 0);
    sgemm_kernel<true><<<dim3(CC/64, MT/64, 1), bg>>>(X, wv, V, MT, CC, CC, 1.0f, 0, 0, 0);

    // 3) S = scale * Q @ K^T per batch (M=N=4096, K=256), scale = 1/sqrt(256)
    sgemm_kernel<true><<<dim3(NN/64, NN/64, BB), bg>>>(
        Q, K, S, NN, NN, CC, 0.0625f,
        (long long)NN*CC, (long long)NN*CC, (long long)NN*NN);

    // 4) softmax rows
    softmax_kernel<<<MT, 256>>>();

    // 5) Y = A @ V per batch (M=4096, N=256, K=4096)
    sgemm_kernel<false><<<dim3(CC/64, NN/64, BB), bg>>>(
        S, V, Y, NN, CC, NN, 1.0f,
        (long long)NN*NN, (long long)NN*CC, (long long)NN*CC);

    // 6) (B,N,C) -> (B,C,H,W)
    out_transpose_kernel<<<dim3(NN/32, CC/32, BB), b32>>>(out);
}

// round 3
// speedup vs baseline: 2.7479x; 2.7479x over previous
#include <cuda_runtime.h>
#include <cuda_bf16.h>
#include <stdint.h>
#include <math.h>

#define BB 4
#define CC 256
#define NN 4096          // H*W
#define MT (BB*NN)       // 16384 tokens

// ---------------- device scratch (no allocation) ---------------------------
static __device__ __nv_bfloat16 g_Xh[(size_t)MT*CC], g_Xl[(size_t)MT*CC];
static __device__ __nv_bfloat16 g_Pth[CC*CC], g_Ptl[CC*CC];
static __device__ __nv_bfloat16 g_Wvh[CC*CC], g_Wvl[CC*CC];
static __device__ float         g_T [(size_t)MT*CC];
static __device__ __nv_bfloat16 g_Th[(size_t)MT*CC], g_Tl[(size_t)MT*CC];
static __device__ float         g_V [(size_t)MT*CC];
static __device__ __nv_bfloat16 g_Vth[(size_t)MT*CC], g_Vtl[(size_t)MT*CC];
static __device__ float         g_S [(size_t)BB*NN*NN];       // 256 MB
static __device__ __nv_bfloat16 g_Sh[(size_t)BB*NN*NN];       // 128 MB
static __device__ __nv_bfloat16 g_Sl[(size_t)BB*NN*NN];       // 128 MB
static __device__ float         g_Y [(size_t)MT*CC];

// ---------------- PTX helpers (base features only, no 'a' suffix) ----------
__device__ __forceinline__ uint32_t smem_u32(const void* p){
  uint32_t a;
  asm("{ .reg .u64 t; cvta.to.shared.u64 t, %1; cvt.u32.u64 %0, t; }" : "=r"(a) : "l"(p));
  return a;
}
__device__ __forceinline__ void cp_async16(uint32_t dst, const void* src){
  asm volatile("cp.async.cg.shared.global [%0], [%1], 16;" :: "r"(dst), "l"(src));
}
__device__ __forceinline__ void cp_commit(){
  asm volatile("cp.async.commit_group;" ::: "memory");
}
__device__ __forceinline__ void cp_wait0(){
  asm volatile("cp.async.wait_group 0;" ::: "memory");
}
__device__ __forceinline__ void cp_wait1(){
  asm volatile("cp.async.wait_group 1;" ::: "memory");
}
__device__ __forceinline__ void ldm4(uint32_t& r0, uint32_t& r1, uint32_t& r2,
                                     uint32_t& r3, uint32_t a){
  asm volatile("ldmatrix.sync.aligned.m8n8.x4.shared.b16 {%0,%1,%2,%3}, [%4];"
   : "=r"(r0), "=r"(r1), "=r"(r2), "=r"(r3) : "r"(a));
}
__device__ __forceinline__ void mma16816(float* d, const uint32_t* a, const uint32_t* b){
  asm volatile("mma.sync.aligned.m16n8k16.row.col.f32.bf16.bf16.f32 "
   "{%0,%1,%2,%3}, {%4,%5,%6,%7}, {%8,%9}, {%0,%1,%2,%3};"
   : "+f"(d[0]), "+f"(d[1]), "+f"(d[2]), "+f"(d[3])
   : "r"(a[0]), "r"(a[1]), "r"(a[2]), "r"(a[3]), "r"(b[0]), "r"(b[1]));
}
__device__ __forceinline__ void split2(float x, __nv_bfloat16* h, __nv_bfloat16* l){
  __nv_bfloat16 hh = __float2bfloat16(x);
  *h = hh;
  *l = __float2bfloat16(x - __bfloat162float(hh));
}

// ---------------- kernel: x + PE -> split bf16 (B,N,C) ---------------------
__global__ void pe_transpose_kernel(const float* __restrict__ x) {
    __shared__ float tile[32][33];
    int b  = blockIdx.z;
    int c0 = blockIdx.y * 32, n0 = blockIdx.x * 32;
    int tx = threadIdx.x, ty = threadIdx.y;
    tile[ty][tx] = x[((size_t)(b*CC + c0 + ty))*NN + n0 + tx];
    __syncthreads();
    int c = c0 + tx, n = n0 + ty;
    int h = n >> 6, w = n & 63;
    int pos, cc;
    if (c < 128) { pos = w; cc = c; } else { pos = h; cc = c - 128; }
    int j = cc & 63;
    float inv = expf(-0.14391156831212787f * (float)j);
    float arg = (float)pos * inv;
    float pe = (cc >= 64) ? cosf(arg) : sinf(arg);
    float v = tile[tx][ty] + pe;
    size_t o = ((size_t)(b*NN + n))*CC + c;
    split2(v, &g_Xh[o], &g_Xl[o]);
}

// ---------------- kernel: Pt[e,c] = sum_d Wq[d,c]*Wk[d,e] ------------------
__global__ void pt_kernel(const float* __restrict__ wq, const float* __restrict__ wk){
  int e = blockIdx.x, c = threadIdx.x;
  float acc = 0.f;
  for (int d = 0; d < CC; d++)
    acc += wq[d*CC + c] * wk[d*CC + e];
  int o = e*CC + c;
  split2(acc, &g_Pth[o], &g_Ptl[o]);
}

__global__ void splitW_kernel(const float* __restrict__ wv){
  int i = blockIdx.x*256 + threadIdx.x;
  split2(wv[i], &g_Wvh[i], &g_Wvl[i]);
}

__global__ void splitT_kernel(){
  size_t i = (size_t)blockIdx.x*256 + threadIdx.x;
  split2(g_T[i], &g_Th[i], &g_Tl[i]);
}

// ---------------- kernel: V (B,N,C) -> Vt split (B,C,N) --------------------
__global__ void vtrans_kernel(){
  __shared__ float tile[32][33];
  int b  = blockIdx.z;
  int c0 = blockIdx.y * 32, n0 = blockIdx.x * 32;
  int tx = threadIdx.x, ty = threadIdx.y;
  tile[ty][tx] = g_V[((size_t)(b*NN + n0 + ty))*CC + c0 + tx];
  __syncthreads();
  size_t o = ((size_t)(b*CC + c0 + ty))*NN + n0 + tx;
  split2(tile[tx][ty], &g_Vth[o], &g_Vtl[o]);
}

// ---------------- mma.sync split-bf16 GEMM (NT): C = alpha * A @ B^T -------
// C[m][n] = alpha * sum_k A[m][k]*B[n][k], with A,B pre-split hi/lo bf16 and
// products hi*hi + hi*lo + lo*hi accumulated in fp32.
// CTA tile 128x128, BK=64, 8 warps (64x32 each), cp.async double buffer.
__global__ void __launch_bounds__(256, 1)
gemm_mma(const __nv_bfloat16* __restrict__ Ah, const __nv_bfloat16* __restrict__ Al,
         const __nv_bfloat16* __restrict__ Bh, const __nv_bfloat16* __restrict__ Bl,
         float* __restrict__ Cm,
         int lda, int ldb, int ldc, int K, float alpha,
         long long sA, long long sB, long long sC)
{
  extern __shared__ char sm[];
  const int tid  = threadIdx.x;
  const int lane = tid & 31, wid = tid >> 5;
  const int wm   = (wid >> 2) * 64;       // warp m offset: 0 or 64
  const int wn   = (wid & 3) * 32;        // warp n offset: 0,32,64,96

  const long long bz = blockIdx.z;
  Ah += bz*sA; Al += bz*sA; Bh += bz*sB; Bl += bz*sB; Cm += bz*sC;
  const int m0 = blockIdx.y * 128, n0 = blockIdx.x * 128;

  const __nv_bfloat16* aH = Ah + (size_t)m0 * lda;
  const __nv_bfloat16* aL = Al + (size_t)m0 * lda;
  const __nv_bfloat16* bH = Bh + (size_t)n0 * ldb;
  const __nv_bfloat16* bL = Bl + (size_t)n0 * ldb;

  const uint32_t sb = smem_u32(sm);
  // stage layout: [Ah 16K][Al 16K][Bh 16K][Bl 16K] x 2 stages = 128 KB
  // row = 128 bytes (64 bf16); chunk = 16B; swizzle: chunk ^= (row & 7)

  // ---- loader: one K-chunk (64 cols) of A(hi,lo) + B(hi,lo) ----
  auto load_chunk = [&](int ck, int stage){
    const int kt = ck << 6;
    const uint32_t base = sb + stage * 65536;
    #pragma unroll
    for (int u = 0; u < 4; u++){
      int idx = u*256 + tid;
      int r = idx >> 3, c = idx & 7;
      uint32_t dst = base + r*128 + ((c ^ (r & 7)) << 4);
      size_t g = (size_t)r*lda + kt + c*8;
      cp_async16(dst,         aH + g);
      cp_async16(dst + 16384, aL + g);
    }
    #pragma unroll
    for (int u = 0; u < 4; u++){
      int idx = u*256 + tid;
      int r = idx >> 3, c = idx & 7;
      uint32_t dst = base + 32768 + r*128 + ((c ^ (r & 7)) << 4);
      size_t g = (size_t)r*ldb + kt + c*8;
      cp_async16(dst,         bH + g);
      cp_async16(dst + 16384, bL + g);
    }
    cp_commit();
  };

  float acc[4][4][4] = {};   // [mt][nt][frag]

  const int nchunk = K >> 6;
  load_chunk(0, 0);

  for (int ck = 0; ck < nchunk; ck++){
    const int st = ck & 1;
    if (ck + 1 < nchunk){ load_chunk(ck + 1, st ^ 1); cp_wait1(); }
    else                { cp_wait0(); }
    __syncthreads();

    const uint32_t Abase = sb + st * 65536;
    const uint32_t Bbase = Abase + 32768;
    const int rsel = lane & 15;
    const int csel = lane >> 4;

    #pragma unroll
    for (int ks = 0; ks < 4; ks++){
      const int cA = ks*2 + csel;
      // A fragments (4 m-tiles, hi+lo)
      uint32_t ahf[4][4], alf[4][4];
      #pragma unroll
      for (int mt = 0; mt < 4; mt++){
        int row = wm + mt*16 + rsel;
        uint32_t ad = Abase + row*128 + ((cA ^ (row & 7)) << 4);
        ldm4(ahf[mt][0], ahf[mt][1], ahf[mt][2], ahf[mt][3], ad);
        ldm4(alf[mt][0], alf[mt][1], alf[mt][2], alf[mt][3], ad + 16384);
      }
      // B fragments (4 n8-tiles via 2 x4-loads, hi+lo)
      uint32_t bhf[4][2], blf[4][2];
      #pragma unroll
      for (int g = 0; g < 2; g++){
        int row = wn + g*16 + rsel;
        uint32_t bd = Bbase + row*128 + ((cA ^ (row & 7)) << 4);
        uint32_t r0, r1, r2, r3;
        ldm4(r0, r1, r2, r3, bd);
        bhf[g*2][0] = r0; bhf[g*2][1] = r2;
        bhf[g*2+1][0] = r1; bhf[g*2+1][1] = r3;
        ldm4(r0, r1, r2, r3, bd + 16384);
        blf[g*2][0] = r0; blf[g*2][1] = r2;
        blf[g*2+1][0] = r1; blf[g*2+1][1] = r3;
      }
      #pragma unroll
      for (int mt = 0; mt < 4; mt++)
        #pragma unroll
        for (int nt = 0; nt < 4; nt++){
          mma16816(acc[mt][nt], ahf[mt], bhf[nt]);
          mma16816(acc[mt][nt], ahf[mt], blf[nt]);
          mma16816(acc[mt][nt], alf[mt], bhf[nt]);
        }
    }
    __syncthreads();
  }

  // ---- epilogue: direct float2 stores ----
  #pragma unroll
  for (int mt = 0; mt < 4; mt++){
    #pragma unroll
    for (int nt = 0; nt < 4; nt++){
      int r = m0 + wm + mt*16 + (lane >> 2);
      int c = n0 + wn + nt*8  + (lane & 3)*2;
      float2 v0 = make_float2(acc[mt][nt][0]*alpha, acc[mt][nt][1]*alpha);
      float2 v1 = make_float2(acc[mt][nt][2]*alpha, acc[mt][nt][3]*alpha);
      *(float2*)(Cm + (size_t)r*ldc + c)     = v0;
      *(float2*)(Cm + (size_t)(r+8)*ldc + c) = v1;
    }
  }
}

// ---------------- softmax rows of g_S, write split bf16 --------------------
__global__ void __launch_bounds__(256)
softmax_kernel() {
    size_t row = blockIdx.x;
    const float* p = g_S + row * (size_t)NN;
    int t = threadIdx.x;
    float v[16];
    float mx = -INFINITY;
    #pragma unroll
    for (int i = 0; i < 16; i++) { v[i] = p[t + i*256]; mx = fmaxf(mx, v[i]); }

    __shared__ float red[256];
    red[t] = mx; __syncthreads();
    for (int s = 128; s > 0; s >>= 1) {
        if (t < s) red[t] = fmaxf(red[t], red[t + s]);
        __syncthreads();
    }
    mx = red[0]; __syncthreads();

    float sum = 0.f;
    #pragma unroll
    for (int i = 0; i < 16; i++) { v[i] = expf(v[i] - mx); sum += v[i]; }
    red[t] = sum; __syncthreads();
    for (int s = 128; s > 0; s >>= 1) {
        if (t < s) red[t] += red[t + s];
        __syncthreads();
    }
    float inv = 1.0f / red[0];
    #pragma unroll
    for (int i = 0; i < 16; i++) {
        size_t idx = row * (size_t)NN + t + i*256;
        split2(v[i] * inv, &g_Sh[idx], &g_Sl[idx]);
    }
}

// ---------------- kernel: Y (B,N,C) -> out (B,C,H,W) -----------------------
__global__ void out_transpose_kernel(float* __restrict__ out) {
    __shared__ float tile[32][33];
    int b  = blockIdx.z;
    int c0 = blockIdx.y * 32, n0 = blockIdx.x * 32;
    int tx = threadIdx.x, ty = threadIdx.y;
    tile[ty][tx] = g_Y[((size_t)(b*NN + n0 + ty))*CC + c0 + tx];
    __syncthreads();
    out[((size_t)(b*CC + c0 + ty))*NN + n0 + tx] = tile[tx][ty];
}

// ---------------- launch ----------------------------------------------------
extern "C" void kernel_launch(void* const* d_in, const int* in_sizes, int n_in,
                              void* d_out, int out_size)
{
    const float* x  = (const float*)d_in[0];
    const float* wq = (const float*)d_in[1];
    const float* wk = (const float*)d_in[2];
    const float* wv = (const float*)d_in[3];
    float* out = (float*)d_out;

    __nv_bfloat16 *Xh, *Xl, *Pth, *Ptl, *Wvh, *Wvl, *Th, *Tl, *Vth, *Vtl, *Sh, *Sl;
    float *T, *V, *S, *Y;
    cudaGetSymbolAddress((void**)&Xh, g_Xh);  cudaGetSymbolAddress((void**)&Xl, g_Xl);
    cudaGetSymbolAddress((void**)&Pth, g_Pth); cudaGetSymbolAddress((void**)&Ptl, g_Ptl);
    cudaGetSymbolAddress((void**)&Wvh, g_Wvh); cudaGetSymbolAddress((void**)&Wvl, g_Wvl);
    cudaGetSymbolAddress((void**)&T,  g_T);
    cudaGetSymbolAddress((void**)&Th, g_Th);  cudaGetSymbolAddress((void**)&Tl, g_Tl);
    cudaGetSymbolAddress((void**)&V,  g_V);
    cudaGetSymbolAddress((void**)&Vth, g_Vth); cudaGetSymbolAddress((void**)&Vtl, g_Vtl);
    cudaGetSymbolAddress((void**)&S,  g_S);
    cudaGetSymbolAddress((void**)&Sh, g_Sh);  cudaGetSymbolAddress((void**)&Sl, g_Sl);
    cudaGetSymbolAddress((void**)&Y,  g_Y);

    const int SMEM = 2 * 65536;   // 128 KB dynamic
    cudaFuncSetAttribute((const void*)gemm_mma,
        cudaFuncAttributeMaxDynamicSharedMemorySize, SMEM);

    // 1) X = x + PE, split bf16, (B,N,C)
    pe_transpose_kernel<<<dim3(NN/32, CC/32, BB), dim3(32,32)>>>(x);

    // 2) Pt = Wq^T Wk (split), Wv split
    pt_kernel<<<CC, CC>>>(wq, wk);
    splitW_kernel<<<CC*CC/256, 256>>>(wv);

    // 3) T = X @ Pt^T (fp32 out), then split
    gemm_mma<<<dim3(CC/128, MT/128, 1), 256, SMEM>>>(
        Xh, Xl, Pth, Ptl, T, CC, CC, CC, CC, 1.0f, 0, 0, 0);
    splitT_kernel<<<(int)((size_t)MT*CC/256), 256>>>();

    // 4) V = X @ Wv^T, then transpose-split to (B,C,N)
    gemm_mma<<<dim3(CC/128, MT/128, 1), 256, SMEM>>>(
        Xh, Xl, Wvh, Wvl, V, CC, CC, CC, CC, 1.0f, 0, 0, 0);
    vtrans_kernel<<<dim3(NN/32, CC/32, BB), dim3(32,32)>>>();

    // 5) S = 0.0625 * T @ X^T per batch
    gemm_mma<<<dim3(NN/128, NN/128, BB), 256, SMEM>>>(
        Th, Tl, Xh, Xl, S, CC, CC, NN, CC, 0.0625f,
        (long long)NN*CC, (long long)NN*CC, (long long)NN*NN);

    // 6) softmax rows -> split bf16
    softmax_kernel<<<MT, 256>>>();

    // 7) Y = A @ Vt^T per batch
    gemm_mma<<<dim3(CC/128, NN/128, BB), 256, SMEM>>>(
        Sh, Sl, Vth, Vtl, Y, NN, NN, CC, NN, 1.0f,
        (long long)NN*NN, (long long)CC*NN, (long long)NN*CC);

    // 8) (B,N,C) -> (B,C,H,W)
    out_transpose_kernel<<<dim3(NN/32, CC/32, BB), dim3(32,32)>>>(out);
}

// round 4
// speedup vs baseline: 2.8312x; 1.0303x over previous
#include <cuda_runtime.h>
#include <cuda_bf16.h>
#include <stdint.h>
#include <math.h>

#define BB 4
#define CC 256
#define NN 4096          // H*W
#define MT (BB*NN)       // 16384 tokens
#define BQ 64            // queries per CTA (flash)
#define BKC 64           // keys per chunk (flash)
#define NCH (NN/BKC)     // 64 chunks

// ---------------- device scratch (no allocation) ---------------------------
static __device__ __nv_bfloat16 g_Xh[(size_t)MT*CC], g_Xl[(size_t)MT*CC];
static __device__ __nv_bfloat16 g_Pth[CC*CC], g_Ptl[CC*CC];
static __device__ __nv_bfloat16 g_Wvh[CC*CC], g_Wvl[CC*CC];
static __device__ __nv_bfloat16 g_Th[(size_t)MT*CC], g_Tl[(size_t)MT*CC];
static __device__ float         g_V [(size_t)MT*CC];
static __device__ __nv_bfloat16 g_Vth[(size_t)MT*CC], g_Vtl[(size_t)MT*CC];
static __device__ float         g_Y [(size_t)MT*CC];

// ---------------- PTX helpers (base features only) -------------------------
__device__ __forceinline__ uint32_t smem_u32(const void* p){
  uint32_t a;
  asm("{ .reg .u64 t; cvta.to.shared.u64 t, %1; cvt.u32.u64 %0, t; }" : "=r"(a) : "l"(p));
  return a;
}
__device__ __forceinline__ void cp_async16(uint32_t dst, const void* src){
  asm volatile("cp.async.cg.shared.global [%0], [%1], 16;" :: "r"(dst), "l"(src));
}
__device__ __forceinline__ void cp_commit(){
  asm volatile("cp.async.commit_group;" ::: "memory");
}
__device__ __forceinline__ void cp_wait0(){
  asm volatile("cp.async.wait_group 0;" ::: "memory");
}
__device__ __forceinline__ void cp_wait1(){
  asm volatile("cp.async.wait_group 1;" ::: "memory");
}
__device__ __forceinline__ void ldm4(uint32_t& r0, uint32_t& r1, uint32_t& r2,
                                     uint32_t& r3, uint32_t a){
  asm volatile("ldmatrix.sync.aligned.m8n8.x4.shared.b16 {%0,%1,%2,%3}, [%4];"
   : "=r"(r0), "=r"(r1), "=r"(r2), "=r"(r3) : "r"(a));
}
__device__ __forceinline__ void mma16816(float* d, const uint32_t* a, const uint32_t* b){
  asm volatile("mma.sync.aligned.m16n8k16.row.col.f32.bf16.bf16.f32 "
   "{%0,%1,%2,%3}, {%4,%5,%6,%7}, {%8,%9}, {%0,%1,%2,%3};"
   : "+f"(d[0]), "+f"(d[1]), "+f"(d[2]), "+f"(d[3])
   : "r"(a[0]), "r"(a[1]), "r"(a[2]), "r"(a[3]), "r"(b[0]), "r"(b[1]));
}
__device__ __forceinline__ void split2(float x, __nv_bfloat16* h, __nv_bfloat16* l){
  __nv_bfloat16 hh = __float2bfloat16(x);
  *h = hh;
  *l = __float2bfloat16(x - __bfloat162float(hh));
}

// ---------------- kernel: x + PE -> split bf16 (B,N,C) ---------------------
__global__ void pe_transpose_kernel(const float* __restrict__ x) {
    __shared__ float tile[32][33];
    int b  = blockIdx.z;
    int c0 = blockIdx.y * 32, n0 = blockIdx.x * 32;
    int tx = threadIdx.x, ty = threadIdx.y;
    tile[ty][tx] = x[((size_t)(b*CC + c0 + ty))*NN + n0 + tx];
    __syncthreads();
    int c = c0 + tx, n = n0 + ty;
    int h = n >> 6, w = n & 63;
    int pos, cc;
    if (c < 128) { pos = w; cc = c; } else { pos = h; cc = c - 128; }
    int j = cc & 63;
    float inv = expf(-0.14391156831212787f * (float)j);
    float arg = (float)pos * inv;
    float pe = (cc >= 64) ? cosf(arg) : sinf(arg);
    float v = tile[tx][ty] + pe;
    size_t o = ((size_t)(b*NN + n))*CC + c;
    split2(v, &g_Xh[o], &g_Xl[o]);
}

// ---------------- kernel: Pt[e,c] = sum_d Wq[d,c]*Wk[d,e] ------------------
__global__ void pt_kernel(const float* __restrict__ wq, const float* __restrict__ wk){
  int e = blockIdx.x, c = threadIdx.x;
  float acc = 0.f;
  for (int d = 0; d < CC; d++)
    acc += wq[d*CC + c] * wk[d*CC + e];
  int o = e*CC + c;
  split2(acc, &g_Pth[o], &g_Ptl[o]);
}

__global__ void splitW_kernel(const float* __restrict__ wv){
  int i = blockIdx.x*256 + threadIdx.x;
  split2(wv[i], &g_Wvh[i], &g_Wvl[i]);
}

// ---------------- kernel: V (B,N,C) -> Vt split (B,C,N) --------------------
__global__ void vtrans_kernel(){
  __shared__ float tile[32][33];
  int b  = blockIdx.z;
  int c0 = blockIdx.y * 32, n0 = blockIdx.x * 32;
  int tx = threadIdx.x, ty = threadIdx.y;
  tile[ty][tx] = g_V[((size_t)(b*NN + n0 + ty))*CC + c0 + tx];
  __syncthreads();
  size_t o = ((size_t)(b*CC + c0 + ty))*NN + n0 + tx;
  split2(tile[tx][ty], &g_Vth[o], &g_Vtl[o]);
}

// ---------------- mma.sync split-bf16 GEMM (NT) -----------------------------
// CTA tile 128x128, BK=64, 8 warps (64x32), cp.async double buffer.
// SPLIT=false: fp32 out to Cm.  SPLIT=true: bf16 hi/lo out to Ch/Cl.
template<bool SPLIT>
__global__ void __launch_bounds__(256, 1)
gemm_mma(const __nv_bfloat16* __restrict__ Ah, const __nv_bfloat16* __restrict__ Al,
         const __nv_bfloat16* __restrict__ Bh, const __nv_bfloat16* __restrict__ Bl,
         float* __restrict__ Cm, __nv_bfloat16* __restrict__ Ch,
         __nv_bfloat16* __restrict__ Cl,
         int lda, int ldb, int ldc, int K, float alpha)
{
  extern __shared__ char sm[];
  const int tid  = threadIdx.x;
  const int lane = tid & 31, wid = tid >> 5;
  const int wm   = (wid >> 2) * 64;
  const int wn   = (wid & 3) * 32;

  const int m0 = blockIdx.y * 128, n0 = blockIdx.x * 128;
  const __nv_bfloat16* aH = Ah + (size_t)m0 * lda;
  const __nv_bfloat16* aL = Al + (size_t)m0 * lda;
  const __nv_bfloat16* bH = Bh + (size_t)n0 * ldb;
  const __nv_bfloat16* bL = Bl + (size_t)n0 * ldb;

  const uint32_t sb = smem_u32(sm);

  auto load_chunk = [&](int ck, int stage){
    const int kt = ck << 6;
    const uint32_t base = sb + stage * 65536;
    #pragma unroll
    for (int u = 0; u < 4; u++){
      int idx = u*256 + tid;
      int r = idx >> 3, c = idx & 7;
      uint32_t dst = base + r*128 + ((c ^ (r & 7)) << 4);
      size_t g = (size_t)r*lda + kt + c*8;
      cp_async16(dst,         aH + g);
      cp_async16(dst + 16384, aL + g);
    }
    #pragma unroll
    for (int u = 0; u < 4; u++){
      int idx = u*256 + tid;
      int r = idx >> 3, c = idx & 7;
      uint32_t dst = sb + stage*65536 + 32768 + r*128 + ((c ^ (r & 7)) << 4);
      size_t g = (size_t)r*ldb + kt + c*8;
      cp_async16(dst,         bH + g);
      cp_async16(dst + 16384, bL + g);
    }
    cp_commit();
  };

  float acc[4][4][4] = {};
  const int nchunk = K >> 6;
  load_chunk(0, 0);

  for (int ck = 0; ck < nchunk; ck++){
    const int st = ck & 1;
    if (ck + 1 < nchunk){ load_chunk(ck + 1, st ^ 1); cp_wait1(); }
    else                { cp_wait0(); }
    __syncthreads();

    const uint32_t Abase = sb + st * 65536;
    const uint32_t Bbase = Abase + 32768;
    const int rsel = lane & 15;
    const int csel = lane >> 4;

    #pragma unroll
    for (int ks = 0; ks < 4; ks++){
      const int cA = ks*2 + csel;
      uint32_t ahf[4][4], alf[4][4];
      #pragma unroll
      for (int mt = 0; mt < 4; mt++){
        int row = wm + mt*16 + rsel;
        uint32_t ad = Abase + row*128 + ((cA ^ (row & 7)) << 4);
        ldm4(ahf[mt][0], ahf[mt][1], ahf[mt][2], ahf[mt][3], ad);
        ldm4(alf[mt][0], alf[mt][1], alf[mt][2], alf[mt][3], ad + 16384);
      }
      uint32_t bhf[4][2], blf[4][2];
      #pragma unroll
      for (int g = 0; g < 2; g++){
        int row = wn + g*16 + rsel;
        uint32_t bd = Bbase + row*128 + ((cA ^ (row & 7)) << 4);
        uint32_t r0, r1, r2, r3;
        ldm4(r0, r1, r2, r3, bd);
        bhf[g*2][0] = r0; bhf[g*2][1] = r2;
        bhf[g*2+1][0] = r1; bhf[g*2+1][1] = r3;
        ldm4(r0, r1, r2, r3, bd + 16384);
        blf[g*2][0] = r0; blf[g*2][1] = r2;
        blf[g*2+1][0] = r1; blf[g*2+1][1] = r3;
      }
      #pragma unroll
      for (int mt = 0; mt < 4; mt++)
        #pragma unroll
        for (int nt = 0; nt < 4; nt++){
          mma16816(acc[mt][nt], ahf[mt], bhf[nt]);
          mma16816(acc[mt][nt], ahf[mt], blf[nt]);
          mma16816(acc[mt][nt], alf[mt], bhf[nt]);
        }
    }
    __syncthreads();
  }

  #pragma unroll
  for (int mt = 0; mt < 4; mt++){
    #pragma unroll
    for (int nt = 0; nt < 4; nt++){
      int r = m0 + wm + mt*16 + (lane >> 2);
      int c = n0 + wn + nt*8  + (lane & 3)*2;
      if (SPLIT){
        __nv_bfloat162 h2, l2;
        __nv_bfloat16 h, l;
        split2(acc[mt][nt][0]*alpha, &h, &l); h2.x = h; l2.x = l;
        split2(acc[mt][nt][1]*alpha, &h, &l); h2.y = h; l2.y = l;
        *(__nv_bfloat162*)(Ch + (size_t)r*ldc + c) = h2;
        *(__nv_bfloat162*)(Cl + (size_t)r*ldc + c) = l2;
        split2(acc[mt][nt][2]*alpha, &h, &l); h2.x = h; l2.x = l;
        split2(acc[mt][nt][3]*alpha, &h, &l); h2.y = h; l2.y = l;
        *(__nv_bfloat162*)(Ch + (size_t)(r+8)*ldc + c) = h2;
        *(__nv_bfloat162*)(Cl + (size_t)(r+8)*ldc + c) = l2;
      } else {
        float2 v0 = make_float2(acc[mt][nt][0]*alpha, acc[mt][nt][1]*alpha);
        float2 v1 = make_float2(acc[mt][nt][2]*alpha, acc[mt][nt][3]*alpha);
        *(float2*)(Cm + (size_t)r*ldc + c)     = v0;
        *(float2*)(Cm + (size_t)(r+8)*ldc + c) = v1;
      }
    }
  }
}

// ---------------- fused flash attention ------------------------------------
// Per CTA: 64 queries, stream 64-key chunks. Q=T (pre-scaled), K=X, V=Vt.
// smem: Tq 64K | K 64K | V 64K | P 16K | stats
#define SM_TQH 0
#define SM_TQL 32768
#define SM_KH  65536
#define SM_KL  98304
#define SM_VH  131072
#define SM_VL  163840
#define SM_PH  196608
#define SM_PL  204800
#define SM_ST  212992
#define SM_FLASH (212992 + 2816)

__global__ void __launch_bounds__(256, 1)
flash_kernel()
{
  extern __shared__ char sm[];
  const uint32_t sb = smem_u32(sm);
  float* m_run = (float*)(sm + SM_ST);        // [64]
  float* l_run = m_run + 64;                  // [64]
  float* fsc   = l_run + 64;                  // [64]
  float* cmax  = fsc + 64;                    // [4][64]
  float* csum  = cmax + 256;                  // [4][64]

  const int tid = threadIdx.x, lane = tid & 31, wid = tid >> 5;
  const int b  = blockIdx.y;
  const int q0 = blockIdx.x * BQ;
  const int wm  = (wid >> 2) * 32;     // m-offset (S and PV)
  const int wnS = (wid & 3) * 16;      // S n-offset (keys)
  const int wnV = (wid & 3) * 64;      // PV n-offset (dims)
  const int rsel = lane & 15, csel = lane >> 4;

  if (tid < 64){ m_run[tid] = -1e30f; l_run[tid] = 0.f; }

  auto load_K = [&](int j){
    int k0 = j * BKC;
    #pragma unroll
    for (int u = 0; u < 8; u++){
      int idx = u*256 + tid;            // 64 rows x 32 chunks
      int r = idx >> 5, c = idx & 31;
      uint32_t dst = sb + SM_KH + r*512 + ((c ^ (r & 7)) << 4);
      size_t g = ((size_t)(b*NN + k0 + r))*CC + c*8;
      cp_async16(dst,         g_Xh + g);
      cp_async16(dst + 32768, g_Xl + g);
    }
  };
  auto load_V = [&](int j){
    int k0 = j * BKC;
    #pragma unroll
    for (int u = 0; u < 8; u++){
      int idx = u*256 + tid;            // 256 rows x 8 chunks
      int r = idx >> 3, c = idx & 7;
      uint32_t dst = sb + SM_VH + r*128 + ((c ^ (r & 7)) << 4);
      size_t g = ((size_t)(b*CC + r))*NN + k0 + c*8;
      cp_async16(dst,         g_Vth + g);
      cp_async16(dst + 32768, g_Vtl + g);
    }
  };

  // prologue: Tq + K0 (group 0), V0 (group 1)
  #pragma unroll
  for (int u = 0; u < 8; u++){
    int idx = u*256 + tid;
    int r = idx >> 5, c = idx & 31;
    uint32_t dst = sb + SM_TQH + r*512 + ((c ^ (r & 7)) << 4);
    size_t g = ((size_t)(b*NN + q0 + r))*CC + c*8;
    cp_async16(dst,         g_Th + g);
    cp_async16(dst + 32768, g_Tl + g);
  }
  load_K(0);
  cp_commit();
  load_V(0);
  cp_commit();

  float accY[2][8][4] = {};

  for (int j = 0; j < NCH; j++){
    cp_wait1();               // K_j (and Tq on j=0) complete
    __syncthreads();

    // ---- S = Tq @ K^T (64x64), 3-product split --------------------------
    float accS[2][2][4] = {};
    #pragma unroll 4
    for (int ks = 0; ks < 16; ks++){
      const int cA = ks*2 + csel;
      uint32_t ah[2][4], al[2][4];
      #pragma unroll
      for (int mt = 0; mt < 2; mt++){
        int row = wm + mt*16 + rsel;
        uint32_t ad = sb + SM_TQH + row*512 + ((cA ^ (row & 7)) << 4);
        ldm4(ah[mt][0], ah[mt][1], ah[mt][2], ah[mt][3], ad);
        ldm4(al[mt][0], al[mt][1], al[mt][2], al[mt][3], ad + 32768);
      }
      uint32_t bh[2][2], bl[2][2];
      {
        int row = wnS + rsel;
        uint32_t bd = sb + SM_KH + row*512 + ((cA ^ (row & 7)) << 4);
        uint32_t r0, r1, r2, r3;
        ldm4(r0, r1, r2, r3, bd);
        bh[0][0]=r0; bh[0][1]=r2; bh[1][0]=r1; bh[1][1]=r3;
        ldm4(r0, r1, r2, r3, bd + 32768);
        bl[0][0]=r0; bl[0][1]=r2; bl[1][0]=r1; bl[1][1]=r3;
      }
      #pragma unroll
      for (int mt = 0; mt < 2; mt++)
        #pragma unroll
        for (int nt = 0; nt < 2; nt++){
          mma16816(accS[mt][nt], ah[mt], bh[nt]);
          mma16816(accS[mt][nt], ah[mt], bl[nt]);
          mma16816(accS[mt][nt], al[mt], bh[nt]);
        }
    }

    // ---- chunk row max ----------------------------------------------------
    #pragma unroll
    for (int mt = 0; mt < 2; mt++){
      float mx0 = fmaxf(fmaxf(accS[mt][0][0], accS[mt][0][1]),
                        fmaxf(accS[mt][1][0], accS[mt][1][1]));
      float mx1 = fmaxf(fmaxf(accS[mt][0][2], accS[mt][0][3]),
                        fmaxf(accS[mt][1][2], accS[mt][1][3]));
      mx0 = fmaxf(mx0, __shfl_xor_sync(0xffffffffu, mx0, 1));
      mx0 = fmaxf(mx0, __shfl_xor_sync(0xffffffffu, mx0, 2));
      mx1 = fmaxf(mx1, __shfl_xor_sync(0xffffffffu, mx1, 1));
      mx1 = fmaxf(mx1, __shfl_xor_sync(0xffffffffu, mx1, 2));
      if ((lane & 3) == 0){
        int rA = wm + mt*16 + (lane >> 2);
        cmax[(wid & 3)*64 + rA]     = mx0;
        cmax[(wid & 3)*64 + rA + 8] = mx1;
      }
    }
    __syncthreads();
    if (tid < 64){
      float mc = fmaxf(fmaxf(cmax[tid], cmax[64+tid]),
                       fmaxf(cmax[128+tid], cmax[192+tid]));
      float mo = m_run[tid];
      float mn = fmaxf(mo, mc);
      m_run[tid] = mn;
      fsc[tid] = __expf(mo - mn);
    }
    __syncthreads();

    // ---- P = exp(S - m), split hi/lo to smem, row sums --------------------
    #pragma unroll
    for (int mt = 0; mt < 2; mt++){
      int rA = wm + mt*16 + (lane >> 2);
      int rB = rA + 8;
      float mA = m_run[rA], mB = m_run[rB];
      float s0 = 0.f, s1 = 0.f;
      #pragma unroll
      for (int nt = 0; nt < 2; nt++){
        float p0 = __expf(accS[mt][nt][0] - mA);
        float p1 = __expf(accS[mt][nt][1] - mA);
        float p2 = __expf(accS[mt][nt][2] - mB);
        float p3 = __expf(accS[mt][nt][3] - mB);
        s0 += p0 + p1; s1 += p2 + p3;
        int c0 = wnS + nt*8 + (lane & 3)*2;
        int ch = c0 >> 3, wi = (c0 & 7)*2;
        uint32_t oA = SM_PH + rA*128 + ((ch ^ (rA & 7)) << 4) + wi;
        uint32_t oB = SM_PH + rB*128 + ((ch ^ (rB & 7)) << 4) + wi;
        __nv_bfloat16 h, l;
        __nv_bfloat162 h2, l2;
        split2(p0, &h, &l); h2.x = h; l2.x = l;
        split2(p1, &h, &l); h2.y = h; l2.y = l;
        *(__nv_bfloat162*)(sm + oA) = h2;
        *(__nv_bfloat162*)(sm + oA + 8192) = l2;
        split2(p2, &h, &l); h2.x = h; l2.x = l;
        split2(p3, &h, &l); h2.y = h; l2.y = l;
        *(__nv_bfloat162*)(sm + oB) = h2;
        *(__nv_bfloat162*)(sm + oB + 8192) = l2;
      }
      s0 += __shfl_xor_sync(0xffffffffu, s0, 1);
      s0 += __shfl_xor_sync(0xffffffffu, s0, 2);
      s1 += __shfl_xor_sync(0xffffffffu, s1, 1);
      s1 += __shfl_xor_sync(0xffffffffu, s1, 2);
      if ((lane & 3) == 0){
        csum[(wid & 3)*64 + rA] = s0;
        csum[(wid & 3)*64 + rB] = s1;
      }
    }
    __syncthreads();        // P + csum visible; Kbuf free
    if (tid < 64)
      l_run[tid] = l_run[tid]*fsc[tid]
                 + (csum[tid] + csum[64+tid] + csum[128+tid] + csum[192+tid]);

    if (j + 1 < NCH){ load_K(j + 1); cp_commit(); cp_wait1(); }
    else            { cp_wait0(); }
    __syncthreads();        // V_j ready

    // ---- rescale Y --------------------------------------------------------
    #pragma unroll
    for (int mt = 0; mt < 2; mt++){
      int rA = wm + mt*16 + (lane >> 2);
      float fA = fsc[rA], fB = fsc[rA + 8];
      #pragma unroll
      for (int nt = 0; nt < 8; nt++){
        accY[mt][nt][0] *= fA; accY[mt][nt][1] *= fA;
        accY[mt][nt][2] *= fB; accY[mt][nt][3] *= fB;
      }
    }

    // ---- Y += P @ V (64x256), 3-product split -----------------------------
    #pragma unroll
    for (int ks = 0; ks < 4; ks++){
      const int cA = ks*2 + csel;
      uint32_t ah[2][4], al[2][4];
      #pragma unroll
      for (int mt = 0; mt < 2; mt++){
        int row = wm + mt*16 + rsel;
        uint32_t ad = sb + SM_PH + row*128 + ((cA ^ (row & 7)) << 4);
        ldm4(ah[mt][0], ah[mt][1], ah[mt][2], ah[mt][3], ad);
        ldm4(al[mt][0], al[mt][1], al[mt][2], al[mt][3], ad + 8192);
      }
      uint32_t bh[8][2], bl[8][2];
      #pragma unroll
      for (int g = 0; g < 4; g++){
        int row = wnV + g*16 + rsel;
        uint32_t bd = sb + SM_VH + row*128 + ((cA ^ (row & 7)) << 4);
        uint32_t r0, r1, r2, r3;
        ldm4(r0, r1, r2, r3, bd);
        bh[g*2][0]=r0; bh[g*2][1]=r2; bh[g*2+1][0]=r1; bh[g*2+1][1]=r3;
        ldm4(r0, r1, r2, r3, bd + 32768);
        bl[g*2][0]=r0; bl[g*2][1]=r2; bl[g*2+1][0]=r1; bl[g*2+1][1]=r3;
      }
      #pragma unroll
      for (int mt = 0; mt < 2; mt++)
        #pragma unroll
        for (int nt = 0; nt < 8; nt++){
          mma16816(accY[mt][nt], ah[mt], bh[nt]);
          mma16816(accY[mt][nt], ah[mt], bl[nt]);
          mma16816(accY[mt][nt], al[mt], bh[nt]);
        }
    }
    __syncthreads();        // Vbuf + P free
    if (j + 1 < NCH){ load_V(j + 1); cp_commit(); }
  }

  // ---- final: Y /= l_run, store fp32 (B,N,C) --------------------------------
  #pragma unroll
  for (int mt = 0; mt < 2; mt++){
    int rA = wm + mt*16 + (lane >> 2);
    float iA = 1.0f / l_run[rA], iB = 1.0f / l_run[rA + 8];
    #pragma unroll
    for (int nt = 0; nt < 8; nt++){
      int c = wnV + nt*8 + (lane & 3)*2;
      float2 v0 = make_float2(accY[mt][nt][0]*iA, accY[mt][nt][1]*iA);
      float2 v1 = make_float2(accY[mt][nt][2]*iB, accY[mt][nt][3]*iB);
      *(float2*)(g_Y + ((size_t)(b*NN + q0 + rA))*CC + c)     = v0;
      *(float2*)(g_Y + ((size_t)(b*NN + q0 + rA + 8))*CC + c) = v1;
    }
  }
}

// ---------------- kernel: Y (B,N,C) -> out (B,C,H,W) -----------------------
__global__ void out_transpose_kernel(float* __restrict__ out) {
    __shared__ float tile[32][33];
    int b  = blockIdx.z;
    int c0 = blockIdx.y * 32, n0 = blockIdx.x * 32;
    int tx = threadIdx.x, ty = threadIdx.y;
    tile[ty][tx] = g_Y[((size_t)(b*NN + n0 + ty))*CC + c0 + tx];
    __syncthreads();
    out[((size_t)(b*CC + c0 + ty))*NN + n0 + tx] = tile[tx][ty];
}

// ---------------- launch ----------------------------------------------------
extern "C" void kernel_launch(void* const* d_in, const int* in_sizes, int n_in,
                              void* d_out, int out_size)
{
    const float* x  = (const float*)d_in[0];
    const float* wq = (const float*)d_in[1];
    const float* wk = (const float*)d_in[2];
    const float* wv = (const float*)d_in[3];
    float* out = (float*)d_out;

    __nv_bfloat16 *Xh, *Xl, *Pth, *Ptl, *Wvh, *Wvl, *Th, *Tl;
    float *V;
    cudaGetSymbolAddress((void**)&Xh, g_Xh);  cudaGetSymbolAddress((void**)&Xl, g_Xl);
    cudaGetSymbolAddress((void**)&Pth, g_Pth); cudaGetSymbolAddress((void**)&Ptl, g_Ptl);
    cudaGetSymbolAddress((void**)&Wvh, g_Wvh); cudaGetSymbolAddress((void**)&Wvl, g_Wvl);
    cudaGetSymbolAddress((void**)&Th, g_Th);  cudaGetSymbolAddress((void**)&Tl, g_Tl);
    cudaGetSymbolAddress((void**)&V,  g_V);

    const int SMEM = 2 * 65536;
    cudaFuncSetAttribute((const void*)gemm_mma<true>,
        cudaFuncAttributeMaxDynamicSharedMemorySize, SMEM);
    cudaFuncSetAttribute((const void*)gemm_mma<false>,
        cudaFuncAttributeMaxDynamicSharedMemorySize, SMEM);
    cudaFuncSetAttribute((const void*)flash_kernel,
        cudaFuncAttributeMaxDynamicSharedMemorySize, SM_FLASH);

    // 1) X = x + PE, split bf16, (B,N,C)
    pe_transpose_kernel<<<dim3(NN/32, CC/32, BB), dim3(32,32)>>>(x);

    // 2) Pt = Wq^T Wk (split), Wv split
    pt_kernel<<<CC, CC>>>(wq, wk);
    splitW_kernel<<<CC*CC/256, 256>>>(wv);

    // 3) T = 0.0625 * X @ Pt^T, split output directly
    gemm_mma<true><<<dim3(CC/128, MT/128, 1), 256, SMEM>>>(
        Xh, Xl, Pth, Ptl, nullptr, Th, Tl, CC, CC, CC, CC, 0.0625f);

    // 4) V = X @ Wv^T (fp32), then transpose-split to (B,C,N)
    gemm_mma<false><<<dim3(CC/128, MT/128, 1), 256, SMEM>>>(
        Xh, Xl, Wvh, Wvl, V, nullptr, nullptr, CC, CC, CC, CC, 1.0f);
    vtrans_kernel<<<dim3(NN/32, CC/32, BB), dim3(32,32)>>>();

    // 5) fused flash attention: softmax(T X^T) Vt^T  -> g_Y
    flash_kernel<<<dim3(NN/BQ, BB), 256, SM_FLASH>>>();

    // 6) (B,N,C) -> (B,C,H,W)
    out_transpose_kernel<<<dim3(NN/32, CC/32, BB), dim3(32,32)>>>(out);
}

// round 5
// speedup vs baseline: 4.0025x; 1.4137x over previous
#include <cuda_runtime.h>
#include <cuda_fp16.h>
#include <stdint.h>
#include <math.h>

#define BB 4
#define CC 256
#define NN 4096          // H*W
#define MT (BB*NN)       // 16384 tokens
#define BQ 64            // queries per CTA (flash)
#define BKC 64           // keys per chunk (flash)
#define NCH (NN/BKC)     // 64 chunks

// ---------------- device scratch (no allocation) ---------------------------
static __device__ __half g_Xh[(size_t)MT*CC], g_Xl[(size_t)MT*CC];
static __device__ __half g_Pth[CC*CC], g_Ptl[CC*CC];
static __device__ __half g_Wvh[CC*CC], g_Wvl[CC*CC];
static __device__ __half g_Th[(size_t)MT*CC], g_Tl[(size_t)MT*CC];
static __device__ __half g_Vt[(size_t)MT*CC];              // (B, C, N)

// ---------------- PTX helpers (base features only) -------------------------
__device__ __forceinline__ uint32_t smem_u32(const void* p){
  uint32_t a;
  asm("{ .reg .u64 t; cvta.to.shared.u64 t, %1; cvt.u32.u64 %0, t; }" : "=r"(a) : "l"(p));
  return a;
}
__device__ __forceinline__ void cp_async16(uint32_t dst, const void* src){
  asm volatile("cp.async.cg.shared.global [%0], [%1], 16;" :: "r"(dst), "l"(src));
}
__device__ __forceinline__ void cp_commit(){
  asm volatile("cp.async.commit_group;" ::: "memory");
}
__device__ __forceinline__ void cp_wait0(){
  asm volatile("cp.async.wait_group 0;" ::: "memory");
}
__device__ __forceinline__ void cp_wait1(){
  asm volatile("cp.async.wait_group 1;" ::: "memory");
}
__device__ __forceinline__ void cp_wait3(){
  asm volatile("cp.async.wait_group 3;" ::: "memory");
}
__device__ __forceinline__ void ldm4(uint32_t& r0, uint32_t& r1, uint32_t& r2,
                                     uint32_t& r3, uint32_t a){
  asm volatile("ldmatrix.sync.aligned.m8n8.x4.shared.b16 {%0,%1,%2,%3}, [%4];"
   : "=r"(r0), "=r"(r1), "=r"(r2), "=r"(r3) : "r"(a));
}
__device__ __forceinline__ void mma16816(float* d, const uint32_t* a, const uint32_t* b){
  asm volatile("mma.sync.aligned.m16n8k16.row.col.f32.f16.f16.f32 "
   "{%0,%1,%2,%3}, {%4,%5,%6,%7}, {%8,%9}, {%0,%1,%2,%3};"
   : "+f"(d[0]), "+f"(d[1]), "+f"(d[2]), "+f"(d[3])
   : "r"(a[0]), "r"(a[1]), "r"(a[2]), "r"(a[3]), "r"(b[0]), "r"(b[1]));
}
__device__ __forceinline__ void split2h(float x, __half* h, __half* l){
  __half hh = __float2half_rn(x);
  *h = hh;
  *l = __float2half_rn(x - __half2float(hh));
}

// ---------------- kernel: x + PE -> split fp16 (B,N,C) ---------------------
__global__ void pe_transpose_kernel(const float* __restrict__ x) {
    __shared__ float tile[32][33];
    int b  = blockIdx.z;
    int c0 = blockIdx.y * 32, n0 = blockIdx.x * 32;
    int tx = threadIdx.x, ty = threadIdx.y;
    tile[ty][tx] = x[((size_t)(b*CC + c0 + ty))*NN + n0 + tx];
    __syncthreads();
    int c = c0 + tx, n = n0 + ty;
    int h = n >> 6, w = n & 63;
    int pos, cc;
    if (c < 128) { pos = w; cc = c; } else { pos = h; cc = c - 128; }
    int j = cc & 63;
    float inv = expf(-0.14391156831212787f * (float)j);
    float arg = (float)pos * inv;
    float pe = (cc >= 64) ? cosf(arg) : sinf(arg);
    float v = tile[tx][ty] + pe;
    size_t o = ((size_t)(b*NN + n))*CC + c;
    split2h(v, &g_Xh[o], &g_Xl[o]);
}

// ---------------- kernel: Pt[e,c] = scale * sum_d Wq[d,c]*Wk[d,e] ----------
__global__ void pt_kernel(const float* __restrict__ wq, const float* __restrict__ wk){
  int e = blockIdx.x, c = threadIdx.x;
  float acc = 0.f;
  for (int d = 0; d < CC; d++)
    acc += wq[d*CC + c] * wk[d*CC + e];
  int o = e*CC + c;
  split2h(acc * 0.0625f, &g_Pth[o], &g_Ptl[o]);   // fold softmax scale here
}

__global__ void splitW_kernel(const float* __restrict__ wv){
  int i = blockIdx.x*256 + threadIdx.x;
  split2h(wv[i], &g_Wvh[i], &g_Wvl[i]);
}

// ---------------- mma.sync split-fp16 GEMM (NT), 3-product ------------------
// CTA tile 128x128, BK=64, 8 warps (64x32), cp.async double buffer.
// MODE 0: split fp16 out row-major to O1/O2 (T projection)
// MODE 1: unsplit fp16 out TRANSPOSED to O1 as (B,C,N) (V projection)
template<int MODE>
__global__ void __launch_bounds__(256, 1)
gemm_mma(const __half* __restrict__ Ah, const __half* __restrict__ Al,
         const __half* __restrict__ Bh, const __half* __restrict__ Bl,
         __half* __restrict__ O1, __half* __restrict__ O2,
         int lda, int ldb, int K)
{
  extern __shared__ char sm[];
  const int tid  = threadIdx.x;
  const int lane = tid & 31, wid = tid >> 5;
  const int wm   = (wid >> 2) * 64;
  const int wn   = (wid & 3) * 32;

  const int m0 = blockIdx.y * 128, n0 = blockIdx.x * 128;
  const __half* aH = Ah + (size_t)m0 * lda;
  const __half* aL = Al + (size_t)m0 * lda;
  const __half* bH = Bh + (size_t)n0 * ldb;
  const __half* bL = Bl + (size_t)n0 * ldb;

  const uint32_t sb = smem_u32(sm);

  auto load_chunk = [&](int ck, int stage){
    const int kt = ck << 6;
    const uint32_t base = sb + stage * 65536;
    #pragma unroll
    for (int u = 0; u < 4; u++){
      int idx = u*256 + tid;
      int r = idx >> 3, c = idx & 7;
      uint32_t dst = base + r*128 + ((c ^ (r & 7)) << 4);
      size_t g = (size_t)r*lda + kt + c*8;
      cp_async16(dst,         aH + g);
      cp_async16(dst + 16384, aL + g);
    }
    #pragma unroll
    for (int u = 0; u < 4; u++){
      int idx = u*256 + tid;
      int r = idx >> 3, c = idx & 7;
      uint32_t dst = base + 32768 + r*128 + ((c ^ (r & 7)) << 4);
      size_t g = (size_t)r*ldb + kt + c*8;
      cp_async16(dst,         bH + g);
      cp_async16(dst + 16384, bL + g);
    }
    cp_commit();
  };

  float acc[4][4][4] = {};
  const int nchunk = K >> 6;
  load_chunk(0, 0);

  for (int ck = 0; ck < nchunk; ck++){
    const int st = ck & 1;
    if (ck + 1 < nchunk){ load_chunk(ck + 1, st ^ 1); cp_wait1(); }
    else                { cp_wait0(); }
    __syncthreads();

    const uint32_t Abase = sb + st * 65536;
    const uint32_t Bbase = Abase + 32768;
    const int rsel = lane & 15;
    const int csel = lane >> 4;

    #pragma unroll
    for (int ks = 0; ks < 4; ks++){
      const int cA = ks*2 + csel;
      uint32_t ahf[4][4], alf[4][4];
      #pragma unroll
      for (int mt = 0; mt < 4; mt++){
        int row = wm + mt*16 + rsel;
        uint32_t ad = Abase + row*128 + ((cA ^ (row & 7)) << 4);
        ldm4(ahf[mt][0], ahf[mt][1], ahf[mt][2], ahf[mt][3], ad);
        ldm4(alf[mt][0], alf[mt][1], alf[mt][2], alf[mt][3], ad + 16384);
      }
      uint32_t bhf[4][2], blf[4][2];
      #pragma unroll
      for (int g = 0; g < 2; g++){
        int row = wn + g*16 + rsel;
        uint32_t bd = Bbase + row*128 + ((cA ^ (row & 7)) << 4);
        uint32_t r0, r1, r2, r3;
        ldm4(r0, r1, r2, r3, bd);
        bhf[g*2][0] = r0; bhf[g*2][1] = r2;
        bhf[g*2+1][0] = r1; bhf[g*2+1][1] = r3;
        ldm4(r0, r1, r2, r3, bd + 16384);
        blf[g*2][0] = r0; blf[g*2][1] = r2;
        blf[g*2+1][0] = r1; blf[g*2+1][1] = r3;
      }
      #pragma unroll
      for (int mt = 0; mt < 4; mt++)
        #pragma unroll
        for (int nt = 0; nt < 4; nt++){
          mma16816(acc[mt][nt], ahf[mt], bhf[nt]);
          mma16816(acc[mt][nt], ahf[mt], blf[nt]);
          mma16816(acc[mt][nt], alf[mt], bhf[nt]);
        }
    }
    __syncthreads();
  }

  if (MODE == 0){
    // split fp16 out, row-major (ld = CC)
    #pragma unroll
    for (int mt = 0; mt < 4; mt++)
      #pragma unroll
      for (int nt = 0; nt < 4; nt++){
        int r = m0 + wm + mt*16 + (lane >> 2);
        int c = n0 + wn + nt*8  + (lane & 3)*2;
        __half h, l; __half2 h2, l2;
        split2h(acc[mt][nt][0], &h, &l); h2.x = h; l2.x = l;
        split2h(acc[mt][nt][1], &h, &l); h2.y = h; l2.y = l;
        *(__half2*)(O1 + (size_t)r*CC + c) = h2;
        *(__half2*)(O2 + (size_t)r*CC + c) = l2;
        split2h(acc[mt][nt][2], &h, &l); h2.x = h; l2.x = l;
        split2h(acc[mt][nt][3], &h, &l); h2.y = h; l2.y = l;
        *(__half2*)(O1 + (size_t)(r+8)*CC + c) = h2;
        *(__half2*)(O2 + (size_t)(r+8)*CC + c) = l2;
      }
  } else {
    // transpose via smem: O1[(b*CC + c_global)*NN + token]
    float* stg = (float*)sm;                 // [128 tokens][132]
    #pragma unroll
    for (int mt = 0; mt < 4; mt++)
      #pragma unroll
      for (int nt = 0; nt < 4; nt++){
        int r = wm + mt*16 + (lane >> 2);
        int c = wn + nt*8  + (lane & 3)*2;
        stg[r*132 + c]     = acc[mt][nt][0];
        stg[r*132 + c + 1] = acc[mt][nt][1];
        stg[(r+8)*132 + c]     = acc[mt][nt][2];
        stg[(r+8)*132 + c + 1] = acc[mt][nt][3];
      }
    __syncthreads();
    int b = m0 / NN, tok0 = m0 % NN;
    int cl = tid >> 1, seg = tid & 1;
    size_t base = (size_t)(b*CC + n0 + cl)*NN + tok0 + seg*64;
    #pragma unroll
    for (int i = 0; i < 64; i += 2){
      __half2 hv = __floats2half2_rn(stg[(seg*64 + i)*132 + cl],
                                     stg[(seg*64 + i + 1)*132 + cl]);
      *(__half2*)(O1 + base + i) = hv;
    }
  }
}

// ---------------- fused flash attention ------------------------------------
// Per CTA: 64 queries. Q = T (split hi/lo), K = Xh (unsplit), V = Vt (unsplit).
// 2-product S, 2-product PV. Double-buffered K and V. Writes d_out directly.
#define SM_TQH 0
#define SM_TQL 32768
#define SM_K   65536            // 2 stages x 32768
#define SM_V   131072           // 2 stages x 32768
#define SM_PH  196608
#define SM_PL  204800
#define SM_ST  212992
#define SM_FLASH (212992 + 2816)

__global__ void __launch_bounds__(256, 1)
flash_kernel(float* __restrict__ out)
{
  extern __shared__ char sm[];
  const uint32_t sb = smem_u32(sm);
  float* m_run = (float*)(sm + SM_ST);        // [64]
  float* l_run = m_run + 64;                  // [64]
  float* fsc   = l_run + 64;                  // [64]
  float* cmax  = fsc + 64;                    // [4][64]
  float* csum  = cmax + 256;                  // [4][64]

  const int tid = threadIdx.x, lane = tid & 31, wid = tid >> 5;
  const int b  = blockIdx.y;
  const int q0 = blockIdx.x * BQ;
  const int wm  = (wid >> 2) * 32;     // m-offset
  const int wnS = (wid & 3) * 16;      // S n-offset (keys)
  const int wnV = (wid & 3) * 64;      // PV n-offset (dims)
  const int rsel = lane & 15, csel = lane >> 4;

  if (tid < 64){ m_run[tid] = -1e30f; l_run[tid] = 0.f; }

  auto load_K = [&](int j, int stg){
    int k0 = j * BKC;
    const uint32_t base = sb + SM_K + stg*32768;
    #pragma unroll
    for (int u = 0; u < 8; u++){
      int idx = u*256 + tid;            // 64 rows x 32 chunks
      int r = idx >> 5, c = idx & 31;
      uint32_t dst = base + r*512 + ((c ^ (r & 7)) << 4);
      cp_async16(dst, g_Xh + ((size_t)(b*NN + k0 + r))*CC + c*8);
    }
    cp_commit();
  };
  auto load_V = [&](int j, int stg){
    int k0 = j * BKC;
    const uint32_t base = sb + SM_V + stg*32768;
    #pragma unroll
    for (int u = 0; u < 8; u++){
      int idx = u*256 + tid;            // 256 rows x 8 chunks
      int r = idx >> 3, c = idx & 7;
      uint32_t dst = base + r*128 + ((c ^ (r & 7)) << 4);
      cp_async16(dst, g_Vt + ((size_t)(b*CC + r))*NN + k0 + c*8);
    }
    cp_commit();
  };

  // prologue: {Tq + K0}, {V0}, {K1}, {V1}
  #pragma unroll
  for (int u = 0; u < 8; u++){
    int idx = u*256 + tid;
    int r = idx >> 5, c = idx & 31;
    uint32_t dst = sb + SM_TQH + r*512 + ((c ^ (r & 7)) << 4);
    size_t g = ((size_t)(b*NN + q0 + r))*CC + c*8;
    cp_async16(dst,         g_Th + g);
    cp_async16(dst + 32768, g_Tl + g);
  }
  {
    int k0 = 0;
    const uint32_t base = sb + SM_K;
    #pragma unroll
    for (int u = 0; u < 8; u++){
      int idx = u*256 + tid;
      int r = idx >> 5, c = idx & 31;
      uint32_t dst = base + r*512 + ((c ^ (r & 7)) << 4);
      cp_async16(dst, g_Xh + ((size_t)(b*NN + k0 + r))*CC + c*8);
    }
    cp_commit();
  }
  load_V(0, 0);
  load_K(1, 1);
  load_V(1, 1);

  float accY[2][8][4] = {};

  for (int j = 0; j < NCH; j++){
    const int stg = j & 1;
    cp_wait3();               // K_j (and Tq on j=0) ready
    __syncthreads();

    // ---- S = Tq @ K^T (64x64): (Th + Tl) x K, 2 products ------------------
    float accS[2][2][4] = {};
    const uint32_t Kbase = sb + SM_K + stg*32768;
    #pragma unroll 4
    for (int ks = 0; ks < 16; ks++){
      const int cA = ks*2 + csel;
      uint32_t ah[2][4], al[2][4];
      #pragma unroll
      for (int mt = 0; mt < 2; mt++){
        int row = wm + mt*16 + rsel;
        uint32_t ad = sb + SM_TQH + row*512 + ((cA ^ (row & 7)) << 4);
        ldm4(ah[mt][0], ah[mt][1], ah[mt][2], ah[mt][3], ad);
        ldm4(al[mt][0], al[mt][1], al[mt][2], al[mt][3], ad + 32768);
      }
      uint32_t bh[2][2];
      {
        int row = wnS + rsel;
        uint32_t bd = Kbase + row*512 + ((cA ^ (row & 7)) << 4);
        uint32_t r0, r1, r2, r3;
        ldm4(r0, r1, r2, r3, bd);
        bh[0][0]=r0; bh[0][1]=r2; bh[1][0]=r1; bh[1][1]=r3;
      }
      #pragma unroll
      for (int mt = 0; mt < 2; mt++)
        #pragma unroll
        for (int nt = 0; nt < 2; nt++){
          mma16816(accS[mt][nt], ah[mt], bh[nt]);
          mma16816(accS[mt][nt], al[mt], bh[nt]);
        }
    }

    // ---- chunk row max -----------------------------------------------------
    #pragma unroll
    for (int mt = 0; mt < 2; mt++){
      float mx0 = fmaxf(fmaxf(accS[mt][0][0], accS[mt][0][1]),
                        fmaxf(accS[mt][1][0], accS[mt][1][1]));
      float mx1 = fmaxf(fmaxf(accS[mt][0][2], accS[mt][0][3]),
                        fmaxf(accS[mt][1][2], accS[mt][1][3]));
      mx0 = fmaxf(mx0, __shfl_xor_sync(0xffffffffu, mx0, 1));
      mx0 = fmaxf(mx0, __shfl_xor_sync(0xffffffffu, mx0, 2));
      mx1 = fmaxf(mx1, __shfl_xor_sync(0xffffffffu, mx1, 1));
      mx1 = fmaxf(mx1, __shfl_xor_sync(0xffffffffu, mx1, 2));
      if ((lane & 3) == 0){
        int rA = wm + mt*16 + (lane >> 2);
        cmax[(wid & 3)*64 + rA]     = mx0;
        cmax[(wid & 3)*64 + rA + 8] = mx1;
      }
    }
    __syncthreads();
    if (tid < 64){
      float mc = fmaxf(fmaxf(cmax[tid], cmax[64+tid]),
                       fmaxf(cmax[128+tid], cmax[192+tid]));
      float mo = m_run[tid];
      float mn = fmaxf(mo, mc);
      m_run[tid] = mn;
      fsc[tid] = __expf(mo - mn);
    }
    __syncthreads();

    // ---- P = exp(S - m): split hi/lo fp16 to smem, row sums ----------------
    #pragma unroll
    for (int mt = 0; mt < 2; mt++){
      int rA = wm + mt*16 + (lane >> 2);
      int rB = rA + 8;
      float mA = m_run[rA], mB = m_run[rB];
      float s0 = 0.f, s1 = 0.f;
      #pragma unroll
      for (int nt = 0; nt < 2; nt++){
        float p0 = __expf(accS[mt][nt][0] - mA);
        float p1 = __expf(accS[mt][nt][1] - mA);
        float p2 = __expf(accS[mt][nt][2] - mB);
        float p3 = __expf(accS[mt][nt][3] - mB);
        s0 += p0 + p1; s1 += p2 + p3;
        int c0 = wnS + nt*8 + (lane & 3)*2;
        int ch = c0 >> 3, wi = (c0 & 7)*2;
        uint32_t oA = SM_PH + rA*128 + ((ch ^ (rA & 7)) << 4) + wi;
        uint32_t oB = SM_PH + rB*128 + ((ch ^ (rB & 7)) << 4) + wi;
        __half h, l; __half2 h2, l2;
        split2h(p0, &h, &l); h2.x = h; l2.x = l;
        split2h(p1, &h, &l); h2.y = h; l2.y = l;
        *(__half2*)(sm + oA) = h2;
        *(__half2*)(sm + oA + 8192) = l2;
        split2h(p2, &h, &l); h2.x = h; l2.x = l;
        split2h(p3, &h, &l); h2.y = h; l2.y = l;
        *(__half2*)(sm + oB) = h2;
        *(__half2*)(sm + oB + 8192) = l2;
      }
      s0 += __shfl_xor_sync(0xffffffffu, s0, 1);
      s0 += __shfl_xor_sync(0xffffffffu, s0, 2);
      s1 += __shfl_xor_sync(0xffffffffu, s1, 1);
      s1 += __shfl_xor_sync(0xffffffffu, s1, 2);
      if ((lane & 3) == 0){
        csum[(wid & 3)*64 + rA] = s0;
        csum[(wid & 3)*64 + rB] = s1;
      }
    }
    __syncthreads();            // P + csum visible; K_j consumed
    if (tid < 64)
      l_run[tid] = l_run[tid]*fsc[tid]
                 + (csum[tid] + csum[64+tid] + csum[128+tid] + csum[192+tid]);

    load_K(j + 2 < NCH ? j + 2 : NCH - 1, stg);   // refill K buffer
    cp_wait3();                 // V_j ready
    // (no sync needed: every thread waited; P synced above)

    // ---- rescale Y ----------------------------------------------------------
    #pragma unroll
    for (int mt = 0; mt < 2; mt++){
      int rA = wm + mt*16 + (lane >> 2);
      float fA = fsc[rA], fB = fsc[rA + 8];
      #pragma unroll
      for (int nt = 0; nt < 8; nt++){
        accY[mt][nt][0] *= fA; accY[mt][nt][1] *= fA;
        accY[mt][nt][2] *= fB; accY[mt][nt][3] *= fB;
      }
    }

    // ---- Y += P @ V (64x256): (Ph + Pl) x V, 2 products ---------------------
    const uint32_t Vbase = sb + SM_V + stg*32768;
    #pragma unroll
    for (int ks = 0; ks < 4; ks++){
      const int cA = ks*2 + csel;
      uint32_t ph[2][4], pl[2][4];
      #pragma unroll
      for (int mt = 0; mt < 2; mt++){
        int row = wm + mt*16 + rsel;
        uint32_t ad = sb + SM_PH + row*128 + ((cA ^ (row & 7)) << 4);
        ldm4(ph[mt][0], ph[mt][1], ph[mt][2], ph[mt][3], ad);
        ldm4(pl[mt][0], pl[mt][1], pl[mt][2], pl[mt][3], ad + 8192);
      }
      uint32_t bv[8][2];
      #pragma unroll
      for (int g = 0; g < 4; g++){
        int row = wnV + g*16 + rsel;
        uint32_t bd = Vbase + row*128 + ((cA ^ (row & 7)) << 4);
        uint32_t r0, r1, r2, r3;
        ldm4(r0, r1, r2, r3, bd);
        bv[g*2][0]=r0; bv[g*2][1]=r2; bv[g*2+1][0]=r1; bv[g*2+1][1]=r3;
      }
      #pragma unroll
      for (int mt = 0; mt < 2; mt++)
        #pragma unroll
        for (int nt = 0; nt < 8; nt++){
          mma16816(accY[mt][nt], ph[mt], bv[nt]);
          mma16816(accY[mt][nt], pl[mt], bv[nt]);
        }
    }
    __syncthreads();            // V_j + P consumed
    load_V(j + 2 < NCH ? j + 2 : NCH - 1, stg);   // refill V buffer
  }

  cp_wait0();
  __syncthreads();

  // ---- epilogue: normalize, stage, write out (B,C,H,W) directly -------------
  float* stg = (float*)(sm + SM_K);          // [64 tokens][260]
  #pragma unroll
  for (int mt = 0; mt < 2; mt++){
    int rA = wm + mt*16 + (lane >> 2);
    float iA = 1.0f / l_run[rA], iB = 1.0f / l_run[rA + 8];
    #pragma unroll
    for (int nt = 0; nt < 8; nt++){
      int c = wnV + nt*8 + (lane & 3)*2;
      stg[rA*260 + c]     = accY[mt][nt][0]*iA;
      stg[rA*260 + c + 1] = accY[mt][nt][1]*iA;
      stg[(rA+8)*260 + c]     = accY[mt][nt][2]*iB;
      stg[(rA+8)*260 + c + 1] = accY[mt][nt][3]*iB;
    }
  }
  __syncthreads();
  #pragma unroll
  for (int it = 0; it < 4; it++){
    int crow = it*64 + (tid >> 2);
    int nsg  = (tid & 3) * 16;
    float* op = out + (size_t)(b*CC + crow)*NN + q0 + nsg;
    #pragma unroll
    for (int k = 0; k < 16; k += 4){
      float4 v;
      v.x = stg[(nsg + k + 0)*260 + crow];
      v.y = stg[(nsg + k + 1)*260 + crow];
      v.z = stg[(nsg + k + 2)*260 + crow];
      v.w = stg[(nsg + k + 3)*260 + crow];
      *(float4*)(op + k) = v;
    }
  }
}

// ---------------- launch ----------------------------------------------------
extern "C" void kernel_launch(void* const* d_in, const int* in_sizes, int n_in,
                              void* d_out, int out_size)
{
    const float* x  = (const float*)d_in[0];
    const float* wq = (const float*)d_in[1];
    const float* wk = (const float*)d_in[2];
    const float* wv = (const float*)d_in[3];
    float* out = (float*)d_out;

    __half *Xh, *Xl, *Pth, *Ptl, *Wvh, *Wvl, *Th, *Tl, *Vt;
    cudaGetSymbolAddress((void**)&Xh, g_Xh);  cudaGetSymbolAddress((void**)&Xl, g_Xl);
    cudaGetSymbolAddress((void**)&Pth, g_Pth); cudaGetSymbolAddress((void**)&Ptl, g_Ptl);
    cudaGetSymbolAddress((void**)&Wvh, g_Wvh); cudaGetSymbolAddress((void**)&Wvl, g_Wvl);
    cudaGetSymbolAddress((void**)&Th, g_Th);  cudaGetSymbolAddress((void**)&Tl, g_Tl);
    cudaGetSymbolAddress((void**)&Vt, g_Vt);

    const int SMEM = 2 * 65536;
    cudaFuncSetAttribute((const void*)gemm_mma<0>,
        cudaFuncAttributeMaxDynamicSharedMemorySize, SMEM);
    cudaFuncSetAttribute((const void*)gemm_mma<1>,
        cudaFuncAttributeMaxDynamicSharedMemorySize, SMEM);
    cudaFuncSetAttribute((const void*)flash_kernel,
        cudaFuncAttributeMaxDynamicSharedMemorySize, SM_FLASH);

    // 1) X = x + PE, split fp16, (B,N,C)
    pe_transpose_kernel<<<dim3(NN/32, CC/32, BB), dim3(32,32)>>>(x);

    // 2) Pt = 0.0625 * Wq^T Wk (split), Wv split
    pt_kernel<<<CC, CC>>>(wq, wk);
    splitW_kernel<<<CC*CC/256, 256>>>(wv);

    // 3) T = X @ Pt^T -> split fp16 row-major
    gemm_mma<0><<<dim3(CC/128, MT/128, 1), 256, SMEM>>>(
        Xh, Xl, Pth, Ptl, Th, Tl, CC, CC, CC);

    // 4) Vt = (X @ Wv^T)^T -> unsplit fp16 (B,C,N), fused transpose
    gemm_mma<1><<<dim3(CC/128, MT/128, 1), 256, SMEM>>>(
        Xh, Xl, Wvh, Wvl, Vt, nullptr, CC, CC, CC);

    // 5) fused flash attention -> writes out (B,C,H,W) directly
    flash_kernel<<<dim3(NN/BQ, BB), 256, SM_FLASH>>>(out);
}

// round 6
// speedup vs baseline: 4.7775x; 1.1936x over previous
#include <cuda_runtime.h>
#include <cuda_fp16.h>
#include <stdint.h>
#include <math.h>

#define BB 4
#define CC 256
#define NN 4096          // H*W
#define MT (BB*NN)       // 16384 tokens
#define BQ 128           // queries per CTA (flash)
#define BKC 64           // keys per chunk (flash)
#define NCH (NN/BKC)     // 64 chunks

// ---------------- device scratch (no allocation) ---------------------------
static __device__ __half g_Xh[(size_t)MT*CC], g_Xl[(size_t)MT*CC];
static __device__ __half g_Pth[CC*CC], g_Ptl[CC*CC];
static __device__ __half g_Wvh[CC*CC], g_Wvl[CC*CC];
static __device__ __half g_Th[(size_t)MT*CC], g_Tl[(size_t)MT*CC];
static __device__ __half g_Vt[(size_t)MT*CC];              // (B, C, N)

// ---------------- PTX helpers (base features only) -------------------------
__device__ __forceinline__ uint32_t smem_u32(const void* p){
  uint32_t a;
  asm("{ .reg .u64 t; cvta.to.shared.u64 t, %1; cvt.u32.u64 %0, t; }" : "=r"(a) : "l"(p));
  return a;
}
__device__ __forceinline__ void cp_async16(uint32_t dst, const void* src){
  asm volatile("cp.async.cg.shared.global [%0], [%1], 16;" :: "r"(dst), "l"(src));
}
__device__ __forceinline__ void cp_commit(){
  asm volatile("cp.async.commit_group;" ::: "memory");
}
__device__ __forceinline__ void cp_wait0(){
  asm volatile("cp.async.wait_group 0;" ::: "memory");
}
__device__ __forceinline__ void cp_wait1(){
  asm volatile("cp.async.wait_group 1;" ::: "memory");
}
__device__ __forceinline__ void cp_wait2(){
  asm volatile("cp.async.wait_group 2;" ::: "memory");
}
__device__ __forceinline__ void ldm4(uint32_t& r0, uint32_t& r1, uint32_t& r2,
                                     uint32_t& r3, uint32_t a){
  asm volatile("ldmatrix.sync.aligned.m8n8.x4.shared.b16 {%0,%1,%2,%3}, [%4];"
   : "=r"(r0), "=r"(r1), "=r"(r2), "=r"(r3) : "r"(a));
}
__device__ __forceinline__ void mma16816(float* d, const uint32_t* a, const uint32_t* b){
  asm volatile("mma.sync.aligned.m16n8k16.row.col.f32.f16.f16.f32 "
   "{%0,%1,%2,%3}, {%4,%5,%6,%7}, {%8,%9}, {%0,%1,%2,%3};"
   : "+f"(d[0]), "+f"(d[1]), "+f"(d[2]), "+f"(d[3])
   : "r"(a[0]), "r"(a[1]), "r"(a[2]), "r"(a[3]), "r"(b[0]), "r"(b[1]));
}
__device__ __forceinline__ void split2h(float x, __half* h, __half* l){
  __half hh = __float2half_rn(x);
  *h = hh;
  *l = __float2half_rn(x - __half2float(hh));
}
__device__ __forceinline__ uint32_t pack_h2(__half a, __half b){
  __half2 t; t.x = a; t.y = b;
  return *(uint32_t*)&t;
}

// ---------------- kernel: x + PE -> split fp16 (B,N,C) ---------------------
__global__ void pe_transpose_kernel(const float* __restrict__ x) {
    __shared__ float tile[32][33];
    int b  = blockIdx.z;
    int c0 = blockIdx.y * 32, n0 = blockIdx.x * 32;
    int tx = threadIdx.x, ty = threadIdx.y;
    tile[ty][tx] = x[((size_t)(b*CC + c0 + ty))*NN + n0 + tx];
    __syncthreads();
    int c = c0 + tx, n = n0 + ty;
    int h = n >> 6, w = n & 63;
    int pos, cc;
    if (c < 128) { pos = w; cc = c; } else { pos = h; cc = c - 128; }
    int j = cc & 63;
    float inv = expf(-0.14391156831212787f * (float)j);
    float arg = (float)pos * inv;
    float pe = (cc >= 64) ? cosf(arg) : sinf(arg);
    float v = tile[tx][ty] + pe;
    size_t o = ((size_t)(b*NN + n))*CC + c;
    split2h(v, &g_Xh[o], &g_Xl[o]);
}

// ---------------- kernel: Pt[e,c] = scale * sum_d Wq[d,c]*Wk[d,e] ----------
__global__ void pt_kernel(const float* __restrict__ wq, const float* __restrict__ wk){
  int e = blockIdx.x, c = threadIdx.x;
  float acc = 0.f;
  for (int d = 0; d < CC; d++)
    acc += wq[d*CC + c] * wk[d*CC + e];
  int o = e*CC + c;
  split2h(acc * 0.0625f, &g_Pth[o], &g_Ptl[o]);
}

__global__ void splitW_kernel(const float* __restrict__ wv){
  int i = blockIdx.x*256 + threadIdx.x;
  split2h(wv[i], &g_Wvh[i], &g_Wvl[i]);
}

// ---------------- mma.sync split-fp16 GEMM (NT), 3-product ------------------
// MODE 0: split fp16 out row-major (T projection)
// MODE 1: unsplit fp16 out transposed (B,C,N) (V projection)
template<int MODE>
__global__ void __launch_bounds__(256, 1)
gemm_mma(const __half* __restrict__ Ah, const __half* __restrict__ Al,
         const __half* __restrict__ Bh, const __half* __restrict__ Bl,
         __half* __restrict__ O1, __half* __restrict__ O2,
         int lda, int ldb, int K)
{
  extern __shared__ char sm[];
  const int tid  = threadIdx.x;
  const int lane = tid & 31, wid = tid >> 5;
  const int wm   = (wid >> 2) * 64;
  const int wn   = (wid & 3) * 32;

  const int m0 = blockIdx.y * 128, n0 = blockIdx.x * 128;
  const __half* aH = Ah + (size_t)m0 * lda;
  const __half* aL = Al + (size_t)m0 * lda;
  const __half* bH = Bh + (size_t)n0 * ldb;
  const __half* bL = Bl + (size_t)n0 * ldb;

  const uint32_t sb = smem_u32(sm);

  auto load_chunk = [&](int ck, int stage){
    const int kt = ck << 6;
    const uint32_t base = sb + stage * 65536;
    #pragma unroll
    for (int u = 0; u < 4; u++){
      int idx = u*256 + tid;
      int r = idx >> 3, c = idx & 7;
      uint32_t dst = base + r*128 + ((c ^ (r & 7)) << 4);
      size_t g = (size_t)r*lda + kt + c*8;
      cp_async16(dst,         aH + g);
      cp_async16(dst + 16384, aL + g);
    }
    #pragma unroll
    for (int u = 0; u < 4; u++){
      int idx = u*256 + tid;
      int r = idx >> 3, c = idx & 7;
      uint32_t dst = base + 32768 + r*128 + ((c ^ (r & 7)) << 4);
      size_t g = (size_t)r*ldb + kt + c*8;
      cp_async16(dst,         bH + g);
      cp_async16(dst + 16384, bL + g);
    }
    cp_commit();
  };

  float acc[4][4][4] = {};
  const int nchunk = K >> 6;
  load_chunk(0, 0);

  for (int ck = 0; ck < nchunk; ck++){
    const int st = ck & 1;
    if (ck + 1 < nchunk){ load_chunk(ck + 1, st ^ 1); cp_wait1(); }
    else                { cp_wait0(); }
    __syncthreads();

    const uint32_t Abase = sb + st * 65536;
    const uint32_t Bbase = Abase + 32768;
    const int rsel = lane & 15;
    const int csel = lane >> 4;

    #pragma unroll
    for (int ks = 0; ks < 4; ks++){
      const int cA = ks*2 + csel;
      uint32_t ahf[4][4], alf[4][4];
      #pragma unroll
      for (int mt = 0; mt < 4; mt++){
        int row = wm + mt*16 + rsel;
        uint32_t ad = Abase + row*128 + ((cA ^ (row & 7)) << 4);
        ldm4(ahf[mt][0], ahf[mt][1], ahf[mt][2], ahf[mt][3], ad);
        ldm4(alf[mt][0], alf[mt][1], alf[mt][2], alf[mt][3], ad + 16384);
      }
      uint32_t bhf[4][2], blf[4][2];
      #pragma unroll
      for (int g = 0; g < 2; g++){
        int row = wn + g*16 + rsel;
        uint32_t bd = Bbase + row*128 + ((cA ^ (row & 7)) << 4);
        uint32_t r0, r1, r2, r3;
        ldm4(r0, r1, r2, r3, bd);
        bhf[g*2][0] = r0; bhf[g*2][1] = r2;
        bhf[g*2+1][0] = r1; bhf[g*2+1][1] = r3;
        ldm4(r0, r1, r2, r3, bd + 16384);
        blf[g*2][0] = r0; blf[g*2][1] = r2;
        blf[g*2+1][0] = r1; blf[g*2+1][1] = r3;
      }
      #pragma unroll
      for (int mt = 0; mt < 4; mt++)
        #pragma unroll
        for (int nt = 0; nt < 4; nt++){
          mma16816(acc[mt][nt], ahf[mt], bhf[nt]);
          mma16816(acc[mt][nt], ahf[mt], blf[nt]);
          mma16816(acc[mt][nt], alf[mt], bhf[nt]);
        }
    }
    __syncthreads();
  }

  if (MODE == 0){
    #pragma unroll
    for (int mt = 0; mt < 4; mt++)
      #pragma unroll
      for (int nt = 0; nt < 4; nt++){
        int r = m0 + wm + mt*16 + (lane >> 2);
        int c = n0 + wn + nt*8  + (lane & 3)*2;
        __half h, l; __half2 h2, l2;
        split2h(acc[mt][nt][0], &h, &l); h2.x = h; l2.x = l;
        split2h(acc[mt][nt][1], &h, &l); h2.y = h; l2.y = l;
        *(__half2*)(O1 + (size_t)r*CC + c) = h2;
        *(__half2*)(O2 + (size_t)r*CC + c) = l2;
        split2h(acc[mt][nt][2], &h, &l); h2.x = h; l2.x = l;
        split2h(acc[mt][nt][3], &h, &l); h2.y = h; l2.y = l;
        *(__half2*)(O1 + (size_t)(r+8)*CC + c) = h2;
        *(__half2*)(O2 + (size_t)(r+8)*CC + c) = l2;
      }
  } else {
    float* stg = (float*)sm;
    #pragma unroll
    for (int mt = 0; mt < 4; mt++)
      #pragma unroll
      for (int nt = 0; nt < 4; nt++){
        int r = wm + mt*16 + (lane >> 2);
        int c = wn + nt*8  + (lane & 3)*2;
        stg[r*132 + c]     = acc[mt][nt][0];
        stg[r*132 + c + 1] = acc[mt][nt][1];
        stg[(r+8)*132 + c]     = acc[mt][nt][2];
        stg[(r+8)*132 + c + 1] = acc[mt][nt][3];
      }
    __syncthreads();
    int b = m0 / NN, tok0 = m0 % NN;
    int cl = tid >> 1, seg = tid & 1;
    size_t base = (size_t)(b*CC + n0 + cl)*NN + tok0 + seg*64;
    #pragma unroll
    for (int i = 0; i < 64; i += 2){
      __half2 hv = __floats2half2_rn(stg[(seg*64 + i)*132 + cl],
                                     stg[(seg*64 + i + 1)*132 + cl]);
      *(__half2*)(O1 + base + i) = hv;
    }
  }
}

// ---------------- fused flash attention (warp-local softmax) ---------------
// BQ=128 queries/CTA. 8 warps; warp owns 16 rows x all keys x all dims.
// Q split hi/lo in smem (persistent). K, V in a 3-slot 32KB ring.
// slot(K_j) = (2j)%3, slot(V_j) = (2j+1)%3.
#define SM_QH   0
#define SM_QL   65536
#define SM_RING 131072
#define SM_FLASH (131072 + 3*32768)   // 229376

__global__ void __launch_bounds__(256, 1)
flash_kernel(float* __restrict__ out)
{
  extern __shared__ char sm[];
  const uint32_t sb = smem_u32(sm);
  const int tid = threadIdx.x, lane = tid & 31, wid = tid >> 5;
  const int b  = blockIdx.y;
  const int q0 = blockIdx.x * BQ;
  const int wm = wid * 16;
  const int rsel = lane & 15, csel = lane >> 4;

  auto load_K = [&](int j, int slot){
    int k0 = j * BKC;
    uint32_t base = sb + SM_RING + slot*32768;
    #pragma unroll
    for (int u = 0; u < 8; u++){
      int idx = u*256 + tid;            // 64 rows x 32 chunks
      int r = idx >> 5, c = idx & 31;
      uint32_t dst = base + r*512 + ((c ^ (r & 7)) << 4);
      cp_async16(dst, g_Xh + ((size_t)(b*NN + k0 + r))*CC + c*8);
    }
    cp_commit();
  };
  auto load_V = [&](int j, int slot){
    int k0 = j * BKC;
    uint32_t base = sb + SM_RING + slot*32768;
    #pragma unroll
    for (int u = 0; u < 8; u++){
      int idx = u*256 + tid;            // 256 rows x 8 chunks
      int r = idx >> 3, c = idx & 7;
      uint32_t dst = base + r*128 + ((c ^ (r & 7)) << 4);
      cp_async16(dst, g_Vt + ((size_t)(b*CC + r))*NN + k0 + c*8);
    }
    cp_commit();
  };

  // prologue: Q (hi+lo), K0 -> slot0, V0 -> slot1
  #pragma unroll
  for (int u = 0; u < 16; u++){
    int idx = u*256 + tid;              // 128 rows x 32 chunks
    int r = idx >> 5, c = idx & 31;
    uint32_t dst = sb + SM_QH + r*512 + ((c ^ (r & 7)) << 4);
    size_t g = ((size_t)(b*NN + q0 + r))*CC + c*8;
    cp_async16(dst,         g_Th + g);
    cp_async16(dst + 65536, g_Tl + g);
  }
  cp_commit();
  load_K(0, 0);
  load_V(0, 1);

  float m0r = -1e30f, m1r = -1e30f, l0r = 0.f, l1r = 0.f;
  float accY[32][4] = {};

  for (int j = 0; j < NCH; j++){
    const int jn = (j + 1 < NCH) ? j + 1 : NCH - 1;
    const uint32_t Kbase = sb + SM_RING + ((2*j) % 3)*32768;
    const uint32_t Vbase = sb + SM_RING + ((2*j + 1) % 3)*32768;

    cp_wait1();                 // K_j ready (pending: V_j)
    __syncthreads();            // K_j visible; all warps past PV_{j-1}
    load_K(jn, (2*j + 2) % 3);  // K_{j+1} -> slot of V_{j-1} (free)

    // ---- S = Q @ K^T (warp: 16 rows x 64 keys), 2-product split -----------
    float accS[8][4] = {};
    #pragma unroll 4
    for (int ks = 0; ks < 16; ks++){
      const int cA = ks*2 + csel;
      int qrow = wm + rsel;
      uint32_t ad = sb + SM_QH + qrow*512 + ((cA ^ (qrow & 7)) << 4);
      uint32_t qh[4], ql[4];
      ldm4(qh[0], qh[1], qh[2], qh[3], ad);
      ldm4(ql[0], ql[1], ql[2], ql[3], ad + 65536);
      #pragma unroll
      for (int g = 0; g < 4; g++){
        int krow = g*16 + rsel;
        uint32_t bd = Kbase + krow*512 + ((cA ^ (krow & 7)) << 4);
        uint32_t r0, r1, r2, r3;
        ldm4(r0, r1, r2, r3, bd);
        uint32_t be[2] = {r0, r2}, bo[2] = {r1, r3};
        mma16816(accS[2*g],   qh, be);
        mma16816(accS[2*g],   ql, be);
        mma16816(accS[2*g+1], qh, bo);
        mma16816(accS[2*g+1], ql, bo);
      }
    }

    // ---- warp-local softmax: quad shfl reductions only ---------------------
    float mx0 = -1e30f, mx1 = -1e30f;
    #pragma unroll
    for (int nt = 0; nt < 8; nt++){
      mx0 = fmaxf(mx0, fmaxf(accS[nt][0], accS[nt][1]));
      mx1 = fmaxf(mx1, fmaxf(accS[nt][2], accS[nt][3]));
    }
    mx0 = fmaxf(mx0, __shfl_xor_sync(0xffffffffu, mx0, 1));
    mx0 = fmaxf(mx0, __shfl_xor_sync(0xffffffffu, mx0, 2));
    mx1 = fmaxf(mx1, __shfl_xor_sync(0xffffffffu, mx1, 1));
    mx1 = fmaxf(mx1, __shfl_xor_sync(0xffffffffu, mx1, 2));
    float mn0 = fmaxf(m0r, mx0), mn1 = fmaxf(m1r, mx1);
    float f0 = __expf(m0r - mn0), f1 = __expf(m1r - mn1);
    m0r = mn0; m1r = mn1;

    uint32_t ph[8][2], pl[8][2];
    float s0 = 0.f, s1 = 0.f;
    #pragma unroll
    for (int nt = 0; nt < 8; nt++){
      float p0 = __expf(accS[nt][0] - mn0);
      float p1 = __expf(accS[nt][1] - mn0);
      float p2 = __expf(accS[nt][2] - mn1);
      float p3 = __expf(accS[nt][3] - mn1);
      s0 += p0 + p1; s1 += p2 + p3;
      __half h0, l0, h1, l1;
      split2h(p0, &h0, &l0); split2h(p1, &h1, &l1);
      ph[nt][0] = pack_h2(h0, h1); pl[nt][0] = pack_h2(l0, l1);
      split2h(p2, &h0, &l0); split2h(p3, &h1, &l1);
      ph[nt][1] = pack_h2(h0, h1); pl[nt][1] = pack_h2(l0, l1);
    }
    s0 += __shfl_xor_sync(0xffffffffu, s0, 1);
    s0 += __shfl_xor_sync(0xffffffffu, s0, 2);
    s1 += __shfl_xor_sync(0xffffffffu, s1, 1);
    s1 += __shfl_xor_sync(0xffffffffu, s1, 2);
    l0r = l0r*f0 + s0;
    l1r = l1r*f1 + s1;

    __syncthreads();                 // all warps done reading K_j
    load_V(jn, (2*j) % 3);           // V_{j+1} -> slot of K_j
    cp_wait2();                      // V_j ready (pending: K_{j+1}, V_{j+1})
    __syncthreads();                 // V_j visible

    // ---- rescale Y ----------------------------------------------------------
    #pragma unroll
    for (int nt = 0; nt < 32; nt++){
      accY[nt][0] *= f0; accY[nt][1] *= f0;
      accY[nt][2] *= f1; accY[nt][3] *= f1;
    }

    // ---- Y += P @ V (warp: 16 rows x 256 dims), P from registers ------------
    #pragma unroll
    for (int kv = 0; kv < 4; kv++){
      uint32_t a_h[4] = {ph[2*kv][0], ph[2*kv][1], ph[2*kv+1][0], ph[2*kv+1][1]};
      uint32_t a_l[4] = {pl[2*kv][0], pl[2*kv][1], pl[2*kv+1][0], pl[2*kv+1][1]};
      const int cA = kv*2 + csel;
      #pragma unroll
      for (int g = 0; g < 16; g++){
        int vrow = g*16 + rsel;
        uint32_t bd = Vbase + vrow*128 + ((cA ^ (vrow & 7)) << 4);
        uint32_t r0, r1, r2, r3;
        ldm4(r0, r1, r2, r3, bd);
        uint32_t be[2] = {r0, r2}, bo[2] = {r1, r3};
        mma16816(accY[2*g],   a_h, be);
        mma16816(accY[2*g],   a_l, be);
        mma16816(accY[2*g+1], a_h, bo);
        mma16816(accY[2*g+1], a_l, bo);
      }
    }
    // next iteration's top __syncthreads protects V_j slot reuse
  }

  cp_wait0();
  __syncthreads();

  // ---- epilogue: normalize, stage (reuse Q+ring0), write (B,C,H,W) ----------
  float* stg = (float*)sm;                     // [128 tokens][260]
  {
    float inv0 = 1.0f / l0r, inv1 = 1.0f / l1r;
    int rA = wm + (lane >> 2), rB = rA + 8;
    #pragma unroll
    for (int nt = 0; nt < 32; nt++){
      int c = nt*8 + (lane & 3)*2;
      stg[rA*260 + c]     = accY[nt][0]*inv0;
      stg[rA*260 + c + 1] = accY[nt][1]*inv0;
      stg[rB*260 + c]     = accY[nt][2]*inv1;
      stg[rB*260 + c + 1] = accY[nt][3]*inv1;
    }
  }
  __syncthreads();
  #pragma unroll
  for (int it = 0; it < 4; it++){
    int dim = it*64 + (tid >> 2);
    int seg = (tid & 3) * 32;
    float* op = out + (size_t)(b*CC + dim)*NN + q0 + seg;
    #pragma unroll
    for (int k = 0; k < 32; k += 4){
      float4 v;
      v.x = stg[(seg + k + 0)*260 + dim];
      v.y = stg[(seg + k + 1)*260 + dim];
      v.z = stg[(seg + k + 2)*260 + dim];
      v.w = stg[(seg + k + 3)*260 + dim];
      *(float4*)(op + k) = v;
    }
  }
}

// ---------------- launch ----------------------------------------------------
extern "C" void kernel_launch(void* const* d_in, const int* in_sizes, int n_in,
                              void* d_out, int out_size)
{
    const float* x  = (const float*)d_in[0];
    const float* wq = (const float*)d_in[1];
    const float* wk = (const float*)d_in[2];
    const float* wv = (const float*)d_in[3];
    float* out = (float*)d_out;

    __half *Xh, *Xl, *Pth, *Ptl, *Wvh, *Wvl, *Th, *Tl, *Vt;
    cudaGetSymbolAddress((void**)&Xh, g_Xh);  cudaGetSymbolAddress((void**)&Xl, g_Xl);
    cudaGetSymbolAddress((void**)&Pth, g_Pth); cudaGetSymbolAddress((void**)&Ptl, g_Ptl);
    cudaGetSymbolAddress((void**)&Wvh, g_Wvh); cudaGetSymbolAddress((void**)&Wvl, g_Wvl);
    cudaGetSymbolAddress((void**)&Th, g_Th);  cudaGetSymbolAddress((void**)&Tl, g_Tl);
    cudaGetSymbolAddress((void**)&Vt, g_Vt);

    const int SMEM = 2 * 65536;
    cudaFuncSetAttribute((const void*)gemm_mma<0>,
        cudaFuncAttributeMaxDynamicSharedMemorySize, SMEM);
    cudaFuncSetAttribute((const void*)gemm_mma<1>,
        cudaFuncAttributeMaxDynamicSharedMemorySize, SMEM);
    cudaFuncSetAttribute((const void*)flash_kernel,
        cudaFuncAttributeMaxDynamicSharedMemorySize, SM_FLASH);

    // 1) X = x + PE, split fp16, (B,N,C)
    pe_transpose_kernel<<<dim3(NN/32, CC/32, BB), dim3(32,32)>>>(x);

    // 2) Pt = 0.0625 * Wq^T Wk (split), Wv split
    pt_kernel<<<CC, CC>>>(wq, wk);
    splitW_kernel<<<CC*CC/256, 256>>>(wv);

    // 3) T = X @ Pt^T -> split fp16 row-major
    gemm_mma<0><<<dim3(CC/128, MT/128, 1), 256, SMEM>>>(
        Xh, Xl, Pth, Ptl, Th, Tl, CC, CC, CC);

    // 4) Vt = (X @ Wv^T)^T -> unsplit fp16 (B,C,N)
    gemm_mma<1><<<dim3(CC/128, MT/128, 1), 256, SMEM>>>(
        Xh, Xl, Wvh, Wvl, Vt, nullptr, CC, CC, CC);

    // 5) fused flash attention -> writes out (B,C,H,W) directly
    flash_kernel<<<dim3(NN/BQ, BB), 256, SM_FLASH>>>(out);
}

// round 7
// speedup vs baseline: 7.5111x; 1.5722x over previous
#include <cuda_runtime.h>
#include <cuda_fp16.h>
#include <stdint.h>
#include <math.h>

#define BB 4
#define CC 256
#define NN 4096          // H*W
#define MT (BB*NN)       // 16384 tokens
#define BQ 128           // queries per CTA (flash)
#define BKC 64           // keys per chunk (flash)
#define NCH (NN/BKC)     // 64 chunks

// ---------------- device scratch (no allocation) ---------------------------
static __device__ __half g_Xh[(size_t)MT*CC], g_Xl[(size_t)MT*CC];
static __device__ __half g_Pth[CC*CC], g_Ptl[CC*CC];
static __device__ __half g_Wvh[CC*CC], g_Wvl[CC*CC];
static __device__ __half g_T [(size_t)MT*CC];              // unsplit fp16 Q
static __device__ __half g_Vt[(size_t)MT*CC];              // (B, C, N)

// ---------------- PTX helpers (base features only) -------------------------
__device__ __forceinline__ uint32_t smem_u32(const void* p){
  uint32_t a;
  asm("{ .reg .u64 t; cvta.to.shared.u64 t, %1; cvt.u32.u64 %0, t; }" : "=r"(a) : "l"(p));
  return a;
}
__device__ __forceinline__ void cp_async16(uint32_t dst, const void* src){
  asm volatile("cp.async.cg.shared.global [%0], [%1], 16;" :: "r"(dst), "l"(src));
}
__device__ __forceinline__ void cp_commit(){
  asm volatile("cp.async.commit_group;" ::: "memory");
}
__device__ __forceinline__ void cp_wait0(){
  asm volatile("cp.async.wait_group 0;" ::: "memory");
}
__device__ __forceinline__ void cp_wait1(){
  asm volatile("cp.async.wait_group 1;" ::: "memory");
}
__device__ __forceinline__ void cp_wait2(){
  asm volatile("cp.async.wait_group 2;" ::: "memory");
}
__device__ __forceinline__ void ldm4(uint32_t& r0, uint32_t& r1, uint32_t& r2,
                                     uint32_t& r3, uint32_t a){
  asm volatile("ldmatrix.sync.aligned.m8n8.x4.shared.b16 {%0,%1,%2,%3}, [%4];"
   : "=r"(r0), "=r"(r1), "=r"(r2), "=r"(r3) : "r"(a));
}
__device__ __forceinline__ void mma16816(float* d, const uint32_t* a, const uint32_t* b){
  asm volatile("mma.sync.aligned.m16n8k16.row.col.f32.f16.f16.f32 "
   "{%0,%1,%2,%3}, {%4,%5,%6,%7}, {%8,%9}, {%0,%1,%2,%3};"
   : "+f"(d[0]), "+f"(d[1]), "+f"(d[2]), "+f"(d[3])
   : "r"(a[0]), "r"(a[1]), "r"(a[2]), "r"(a[3]), "r"(b[0]), "r"(b[1]));
}
__device__ __forceinline__ void split2h(float x, __half* h, __half* l){
  __half hh = __float2half_rn(x);
  *h = hh;
  *l = __float2half_rn(x - __half2float(hh));
}
__device__ __forceinline__ uint32_t pack_f2h2(float a, float b){
  __half2 t = __floats2half2_rn(a, b);
  return *(uint32_t*)&t;
}

// ---------------- kernel: x + PE -> split fp16 (B,N,C) ---------------------
__global__ void pe_transpose_kernel(const float* __restrict__ x) {
    __shared__ float tile[32][33];
    int b  = blockIdx.z;
    int c0 = blockIdx.y * 32, n0 = blockIdx.x * 32;
    int tx = threadIdx.x, ty = threadIdx.y;
    tile[ty][tx] = x[((size_t)(b*CC + c0 + ty))*NN + n0 + tx];
    __syncthreads();
    int c = c0 + tx, n = n0 + ty;
    int h = n >> 6, w = n & 63;
    int pos, cc;
    if (c < 128) { pos = w; cc = c; } else { pos = h; cc = c - 128; }
    int j = cc & 63;
    float inv = expf(-0.14391156831212787f * (float)j);
    float arg = (float)pos * inv;
    float pe = (cc >= 64) ? cosf(arg) : sinf(arg);
    float v = tile[tx][ty] + pe;
    size_t o = ((size_t)(b*NN + n))*CC + c;
    split2h(v, &g_Xh[o], &g_Xl[o]);
}

// ---------------- kernel: Pt[e,c] = scale * sum_d Wq[d,c]*Wk[d,e] ----------
__global__ void pt_kernel(const float* __restrict__ wq, const float* __restrict__ wk){
  int e = blockIdx.x, c = threadIdx.x;
  float acc = 0.f;
  for (int d = 0; d < CC; d++)
    acc += wq[d*CC + c] * wk[d*CC + e];
  int o = e*CC + c;
  split2h(acc * 0.0625f, &g_Pth[o], &g_Ptl[o]);
}

__global__ void splitW_kernel(const float* __restrict__ wv){
  int i = blockIdx.x*256 + threadIdx.x;
  split2h(wv[i], &g_Wvh[i], &g_Wvl[i]);
}

// ---------------- mma.sync split-fp16 GEMM (NT), 3-product ------------------
// MODE 0: unsplit fp16 out row-major (T projection)
// MODE 1: unsplit fp16 out transposed (B,C,N) (V projection)
template<int MODE>
__global__ void __launch_bounds__(256, 1)
gemm_mma(const __half* __restrict__ Ah, const __half* __restrict__ Al,
         const __half* __restrict__ Bh, const __half* __restrict__ Bl,
         __half* __restrict__ O1,
         int lda, int ldb, int K)
{
  extern __shared__ char sm[];
  const int tid  = threadIdx.x;
  const int lane = tid & 31, wid = tid >> 5;
  const int wm   = (wid >> 2) * 64;
  const int wn   = (wid & 3) * 32;

  const int m0 = blockIdx.y * 128, n0 = blockIdx.x * 128;
  const __half* aH = Ah + (size_t)m0 * lda;
  const __half* aL = Al + (size_t)m0 * lda;
  const __half* bH = Bh + (size_t)n0 * ldb;
  const __half* bL = Bl + (size_t)n0 * ldb;

  const uint32_t sb = smem_u32(sm);

  auto load_chunk = [&](int ck, int stage){
    const int kt = ck << 6;
    const uint32_t base = sb + stage * 65536;
    #pragma unroll
    for (int u = 0; u < 4; u++){
      int idx = u*256 + tid;
      int r = idx >> 3, c = idx & 7;
      uint32_t dst = base + r*128 + ((c ^ (r & 7)) << 4);
      size_t g = (size_t)r*lda + kt + c*8;
      cp_async16(dst,         aH + g);
      cp_async16(dst + 16384, aL + g);
    }
    #pragma unroll
    for (int u = 0; u < 4; u++){
      int idx = u*256 + tid;
      int r = idx >> 3, c = idx & 7;
      uint32_t dst = base + 32768 + r*128 + ((c ^ (r & 7)) << 4);
      size_t g = (size_t)r*ldb + kt + c*8;
      cp_async16(dst,         bH + g);
      cp_async16(dst + 16384, bL + g);
    }
    cp_commit();
  };

  float acc[4][4][4] = {};
  const int nchunk = K >> 6;
  load_chunk(0, 0);

  for (int ck = 0; ck < nchunk; ck++){
    const int st = ck & 1;
    if (ck + 1 < nchunk){ load_chunk(ck + 1, st ^ 1); cp_wait1(); }
    else                { cp_wait0(); }
    __syncthreads();

    const uint32_t Abase = sb + st * 65536;
    const uint32_t Bbase = Abase + 32768;
    const int rsel = lane & 15;
    const int csel = lane >> 4;

    #pragma unroll
    for (int ks = 0; ks < 4; ks++){
      const int cA = ks*2 + csel;
      uint32_t ahf[4][4], alf[4][4];
      #pragma unroll
      for (int mt = 0; mt < 4; mt++){
        int row = wm + mt*16 + rsel;
        uint32_t ad = Abase + row*128 + ((cA ^ (row & 7)) << 4);
        ldm4(ahf[mt][0], ahf[mt][1], ahf[mt][2], ahf[mt][3], ad);
        ldm4(alf[mt][0], alf[mt][1], alf[mt][2], alf[mt][3], ad + 16384);
      }
      uint32_t bhf[4][2], blf[4][2];
      #pragma unroll
      for (int g = 0; g < 2; g++){
        int row = wn + g*16 + rsel;
        uint32_t bd = Bbase + row*128 + ((cA ^ (row & 7)) << 4);
        uint32_t r0, r1, r2, r3;
        ldm4(r0, r1, r2, r3, bd);
        bhf[g*2][0] = r0; bhf[g*2][1] = r2;
        bhf[g*2+1][0] = r1; bhf[g*2+1][1] = r3;
        ldm4(r0, r1, r2, r3, bd + 16384);
        blf[g*2][0] = r0; blf[g*2][1] = r2;
        blf[g*2+1][0] = r1; blf[g*2+1][1] = r3;
      }
      #pragma unroll
      for (int mt = 0; mt < 4; mt++)
        #pragma unroll
        for (int nt = 0; nt < 4; nt++){
          mma16816(acc[mt][nt], ahf[mt], bhf[nt]);
          mma16816(acc[mt][nt], ahf[mt], blf[nt]);
          mma16816(acc[mt][nt], alf[mt], bhf[nt]);
        }
    }
    __syncthreads();
  }

  if (MODE == 0){
    #pragma unroll
    for (int mt = 0; mt < 4; mt++)
      #pragma unroll
      for (int nt = 0; nt < 4; nt++){
        int r = m0 + wm + mt*16 + (lane >> 2);
        int c = n0 + wn + nt*8  + (lane & 3)*2;
        *(__half2*)(O1 + (size_t)r*CC + c) =
            __floats2half2_rn(acc[mt][nt][0], acc[mt][nt][1]);
        *(__half2*)(O1 + (size_t)(r+8)*CC + c) =
            __floats2half2_rn(acc[mt][nt][2], acc[mt][nt][3]);
      }
  } else {
    float* stg = (float*)sm;
    #pragma unroll
    for (int mt = 0; mt < 4; mt++)
      #pragma unroll
      for (int nt = 0; nt < 4; nt++){
        int r = wm + mt*16 + (lane >> 2);
        int c = wn + nt*8  + (lane & 3)*2;
        stg[r*132 + c]     = acc[mt][nt][0];
        stg[r*132 + c + 1] = acc[mt][nt][1];
        stg[(r+8)*132 + c]     = acc[mt][nt][2];
        stg[(r+8)*132 + c + 1] = acc[mt][nt][3];
      }
    __syncthreads();
    int b = m0 / NN, tok0 = m0 % NN;
    int cl = tid >> 1, seg = tid & 1;
    size_t base = (size_t)(b*CC + n0 + cl)*NN + tok0 + seg*64;
    #pragma unroll
    for (int i = 0; i < 64; i += 2){
      __half2 hv = __floats2half2_rn(stg[(seg*64 + i)*132 + cl],
                                     stg[(seg*64 + i + 1)*132 + cl]);
      *(__half2*)(O1 + base + i) = hv;
    }
  }
}

// ---------------- fused flash attention (warp-local softmax, 1-product) ----
// BQ=128 queries/CTA. 8 warps; warp owns 16 rows x all keys x all dims.
// Q unsplit fp16 in smem (persistent 64KB). K, V in 3-slot 32KB ring.
#define SM_Q    0
#define SM_RING 65536
#define SM_FLASH (65536 + 3*32768)    // 163840

__global__ void __launch_bounds__(256, 1)
flash_kernel(float* __restrict__ out)
{
  extern __shared__ char sm[];
  const uint32_t sb = smem_u32(sm);
  const int tid = threadIdx.x, lane = tid & 31, wid = tid >> 5;
  const int b  = blockIdx.y;
  const int q0 = blockIdx.x * BQ;
  const int wm = wid * 16;
  const int rsel = lane & 15, csel = lane >> 4;

  auto load_K = [&](int j, int slot){
    int k0 = j * BKC;
    uint32_t base = sb + SM_RING + slot*32768;
    #pragma unroll
    for (int u = 0; u < 8; u++){
      int idx = u*256 + tid;            // 64 rows x 32 chunks
      int r = idx >> 5, c = idx & 31;
      uint32_t dst = base + r*512 + ((c ^ (r & 7)) << 4);
      cp_async16(dst, g_Xh + ((size_t)(b*NN + k0 + r))*CC + c*8);
    }
    cp_commit();
  };
  auto load_V = [&](int j, int slot){
    int k0 = j * BKC;
    uint32_t base = sb + SM_RING + slot*32768;
    #pragma unroll
    for (int u = 0; u < 8; u++){
      int idx = u*256 + tid;            // 256 rows x 8 chunks
      int r = idx >> 3, c = idx & 7;
      uint32_t dst = base + r*128 + ((c ^ (r & 7)) << 4);
      cp_async16(dst, g_Vt + ((size_t)(b*CC + r))*NN + k0 + c*8);
    }
    cp_commit();
  };

  // prologue: Q, K0 -> slot0, V0 -> slot1
  #pragma unroll
  for (int u = 0; u < 16; u++){
    int idx = u*256 + tid;              // 128 rows x 32 chunks
    int r = idx >> 5, c = idx & 31;
    uint32_t dst = sb + SM_Q + r*512 + ((c ^ (r & 7)) << 4);
    cp_async16(dst, g_T + ((size_t)(b*NN + q0 + r))*CC + c*8);
  }
  cp_commit();
  load_K(0, 0);
  load_V(0, 1);

  float m0r = -1e30f, m1r = -1e30f, l0r = 0.f, l1r = 0.f;
  float accY[32][4] = {};

  for (int j = 0; j < NCH; j++){
    const int jn = (j + 1 < NCH) ? j + 1 : NCH - 1;
    const uint32_t Kbase = sb + SM_RING + ((2*j) % 3)*32768;
    const uint32_t Vbase = sb + SM_RING + ((2*j + 1) % 3)*32768;

    cp_wait1();                 // K_j ready (pending: V_j)
    __syncthreads();            // K_j visible; all warps past PV_{j-1}
    load_K(jn, (2*j + 2) % 3);  // K_{j+1} -> slot of V_{j-1} (free)

    // ---- S = Q @ K^T (warp: 16 rows x 64 keys), 1-product ------------------
    float accS[8][4] = {};
    #pragma unroll 4
    for (int ks = 0; ks < 16; ks++){
      const int cA = ks*2 + csel;
      int qrow = wm + rsel;
      uint32_t ad = sb + SM_Q + qrow*512 + ((cA ^ (qrow & 7)) << 4);
      uint32_t qh[4];
      ldm4(qh[0], qh[1], qh[2], qh[3], ad);
      #pragma unroll
      for (int g = 0; g < 4; g++){
        int krow = g*16 + rsel;
        uint32_t bd = Kbase + krow*512 + ((cA ^ (krow & 7)) << 4);
        uint32_t r0, r1, r2, r3;
        ldm4(r0, r1, r2, r3, bd);
        uint32_t be[2] = {r0, r2}, bo[2] = {r1, r3};
        mma16816(accS[2*g],   qh, be);
        mma16816(accS[2*g+1], qh, bo);
      }
    }

    // ---- warp-local softmax -------------------------------------------------
    float mx0 = -1e30f, mx1 = -1e30f;
    #pragma unroll
    for (int nt = 0; nt < 8; nt++){
      mx0 = fmaxf(mx0, fmaxf(accS[nt][0], accS[nt][1]));
      mx1 = fmaxf(mx1, fmaxf(accS[nt][2], accS[nt][3]));
    }
    mx0 = fmaxf(mx0, __shfl_xor_sync(0xffffffffu, mx0, 1));
    mx0 = fmaxf(mx0, __shfl_xor_sync(0xffffffffu, mx0, 2));
    mx1 = fmaxf(mx1, __shfl_xor_sync(0xffffffffu, mx1, 1));
    mx1 = fmaxf(mx1, __shfl_xor_sync(0xffffffffu, mx1, 2));
    float mn0 = fmaxf(m0r, mx0), mn1 = fmaxf(m1r, mx1);
    float f0 = __expf(m0r - mn0), f1 = __expf(m1r - mn1);
    m0r = mn0; m1r = mn1;

    uint32_t pp[8][2];
    float s0 = 0.f, s1 = 0.f;
    #pragma unroll
    for (int nt = 0; nt < 8; nt++){
      float p0 = __expf(accS[nt][0] - mn0);
      float p1 = __expf(accS[nt][1] - mn0);
      float p2 = __expf(accS[nt][2] - mn1);
      float p3 = __expf(accS[nt][3] - mn1);
      s0 += p0 + p1; s1 += p2 + p3;
      pp[nt][0] = pack_f2h2(p0, p1);
      pp[nt][1] = pack_f2h2(p2, p3);
    }
    s0 += __shfl_xor_sync(0xffffffffu, s0, 1);
    s0 += __shfl_xor_sync(0xffffffffu, s0, 2);
    s1 += __shfl_xor_sync(0xffffffffu, s1, 1);
    s1 += __shfl_xor_sync(0xffffffffu, s1, 2);
    l0r = l0r*f0 + s0;
    l1r = l1r*f1 + s1;

    __syncthreads();                 // all warps done reading K_j
    load_V(jn, (2*j) % 3);           // V_{j+1} -> slot of K_j
    cp_wait2();                      // V_j ready (pending: K_{j+1}, V_{j+1})
    __syncthreads();                 // V_j visible

    // ---- rescale Y ------------------------------------------------------------
    #pragma unroll
    for (int nt = 0; nt < 32; nt++){
      accY[nt][0] *= f0; accY[nt][1] *= f0;
      accY[nt][2] *= f1; accY[nt][3] *= f1;
    }

    // ---- Y += P @ V (warp: 16 rows x 256 dims), 1-product ----------------------
    #pragma unroll
    for (int kv = 0; kv < 4; kv++){
      uint32_t a_p[4] = {pp[2*kv][0], pp[2*kv][1], pp[2*kv+1][0], pp[2*kv+1][1]};
      const int cA = kv*2 + csel;
      #pragma unroll
      for (int g = 0; g < 16; g++){
        int vrow = g*16 + rsel;
        uint32_t bd = Vbase + vrow*128 + ((cA ^ (vrow & 7)) << 4);
        uint32_t r0, r1, r2, r3;
        ldm4(r0, r1, r2, r3, bd);
        uint32_t be[2] = {r0, r2}, bo[2] = {r1, r3};
        mma16816(accY[2*g],   a_p, be);
        mma16816(accY[2*g+1], a_p, bo);
      }
    }
    // next iteration's top __syncthreads protects V_j slot reuse
  }

  cp_wait0();
  __syncthreads();

  // ---- epilogue: normalize, stage, write (B,C,H,W) ---------------------------
  float* stg = (float*)sm;                     // [128 tokens][260]
  {
    float inv0 = 1.0f / l0r, inv1 = 1.0f / l1r;
    int rA = wm + (lane >> 2), rB = rA + 8;
    #pragma unroll
    for (int nt = 0; nt < 32; nt++){
      int c = nt*8 + (lane & 3)*2;
      stg[rA*260 + c]     = accY[nt][0]*inv0;
      stg[rA*260 + c + 1] = accY[nt][1]*inv0;
      stg[rB*260 + c]     = accY[nt][2]*inv1;
      stg[rB*260 + c + 1] = accY[nt][3]*inv1;
    }
  }
  __syncthreads();
  #pragma unroll
  for (int it = 0; it < 4; it++){
    int dim = it*64 + (tid >> 2);
    int seg = (tid & 3) * 32;
    float* op = out + (size_t)(b*CC + dim)*NN + q0 + seg;
    #pragma unroll
    for (int k = 0; k < 32; k += 4){
      float4 v;
      v.x = stg[(seg + k + 0)*260 + dim];
      v.y = stg[(seg + k + 1)*260 + dim];
      v.z = stg[(seg + k + 2)*260 + dim];
      v.w = stg[(seg + k + 3)*260 + dim];
      *(float4*)(op + k) = v;
    }
  }
}

// ---------------- launch ----------------------------------------------------
extern "C" void kernel_launch(void* const* d_in, const int* in_sizes, int n_in,
                              void* d_out, int out_size)
{
    const float* x  = (const float*)d_in[0];
    const float* wq = (const float*)d_in[1];
    const float* wk = (const float*)d_in[2];
    const float* wv = (const float*)d_in[3];
    float* out = (float*)d_out;

    __half *Xh, *Xl, *Pth, *Ptl, *Wvh, *Wvl, *T, *Vt;
    cudaGetSymbolAddress((void**)&Xh, g_Xh);  cudaGetSymbolAddress((void**)&Xl, g_Xl);
    cudaGetSymbolAddress((void**)&Pth, g_Pth); cudaGetSymbolAddress((void**)&Ptl, g_Ptl);
    cudaGetSymbolAddress((void**)&Wvh, g_Wvh); cudaGetSymbolAddress((void**)&Wvl, g_Wvl);
    cudaGetSymbolAddress((void**)&T,  g_T);
    cudaGetSymbolAddress((void**)&Vt, g_Vt);

    const int SMEM = 2 * 65536;
    cudaFuncSetAttribute((const void*)gemm_mma<0>,
        cudaFuncAttributeMaxDynamicSharedMemorySize, SMEM);
    cudaFuncSetAttribute((const void*)gemm_mma<1>,
        cudaFuncAttributeMaxDynamicSharedMemorySize, SMEM);
    cudaFuncSetAttribute((const void*)flash_kernel,
        cudaFuncAttributeMaxDynamicSharedMemorySize, SM_FLASH);

    // 1) X = x + PE, split fp16, (B,N,C)
    pe_transpose_kernel<<<dim3(NN/32, CC/32, BB), dim3(32,32)>>>(x);

    // 2) Pt = 0.0625 * Wq^T Wk (split), Wv split
    pt_kernel<<<CC, CC>>>(wq, wk);
    splitW_kernel<<<CC*CC/256, 256>>>(wv);

    // 3) T = X @ Pt^T -> fp16 row-major (3-product accuracy inside)
    gemm_mma<0><<<dim3(CC/128, MT/128, 1), 256, SMEM>>>(
        Xh, Xl, Pth, Ptl, T, CC, CC, CC);

    // 4) Vt = (X @ Wv^T)^T -> fp16 (B,C,N)
    gemm_mma<1><<<dim3(CC/128, MT/128, 1), 256, SMEM>>>(
        Xh, Xl, Wvh, Wvl, Vt, CC, CC, CC);

    // 5) fused flash attention -> writes out (B,C,H,W) directly
    flash_kernel<<<dim3(NN/BQ, BB), 256, SM_FLASH>>>(out);
}

// round 8
// speedup vs baseline: 7.6764x; 1.0220x over previous
#include <cuda_runtime.h>
#include <cuda_fp16.h>
#include <stdint.h>
#include <math.h>

#define BB 4
#define CC 256
#define NN 4096          // H*W
#define MT (BB*NN)       // 16384 tokens
#define BQ 128           // queries per CTA (flash)
#define BKC 64           // keys per chunk (flash)
#define NCH (NN/BKC)     // 64 chunks

// ---------------- device scratch (no allocation) ---------------------------
static __device__ __half g_Xh[(size_t)MT*CC], g_Xl[(size_t)MT*CC];
static __device__ __half g_Pt[CC*CC];
static __device__ __half g_Wv[CC*CC];
static __device__ __half g_T [(size_t)MT*CC];              // unsplit fp16 Q
static __device__ __half g_Vt[(size_t)MT*CC];              // (B, C, N)

// ---------------- PTX helpers (base features only) -------------------------
__device__ __forceinline__ uint32_t smem_u32(const void* p){
  uint32_t a;
  asm("{ .reg .u64 t; cvta.to.shared.u64 t, %1; cvt.u32.u64 %0, t; }" : "=r"(a) : "l"(p));
  return a;
}
__device__ __forceinline__ void cp_async16(uint32_t dst, const void* src){
  asm volatile("cp.async.cg.shared.global [%0], [%1], 16;" :: "r"(dst), "l"(src));
}
__device__ __forceinline__ void cp_commit(){
  asm volatile("cp.async.commit_group;" ::: "memory");
}
__device__ __forceinline__ void cp_wait0(){
  asm volatile("cp.async.wait_group 0;" ::: "memory");
}
__device__ __forceinline__ void cp_wait1(){
  asm volatile("cp.async.wait_group 1;" ::: "memory");
}
__device__ __forceinline__ void cp_wait2(){
  asm volatile("cp.async.wait_group 2;" ::: "memory");
}
__device__ __forceinline__ void ldm4(uint32_t& r0, uint32_t& r1, uint32_t& r2,
                                     uint32_t& r3, uint32_t a){
  asm volatile("ldmatrix.sync.aligned.m8n8.x4.shared.b16 {%0,%1,%2,%3}, [%4];"
   : "=r"(r0), "=r"(r1), "=r"(r2), "=r"(r3) : "r"(a));
}
__device__ __forceinline__ void mma16816(float* d, const uint32_t* a, const uint32_t* b){
  asm volatile("mma.sync.aligned.m16n8k16.row.col.f32.f16.f16.f32 "
   "{%0,%1,%2,%3}, {%4,%5,%6,%7}, {%8,%9}, {%0,%1,%2,%3};"
   : "+f"(d[0]), "+f"(d[1]), "+f"(d[2]), "+f"(d[3])
   : "r"(a[0]), "r"(a[1]), "r"(a[2]), "r"(a[3]), "r"(b[0]), "r"(b[1]));
}
__device__ __forceinline__ void split2h(float x, __half* h, __half* l){
  __half hh = __float2half_rn(x);
  *h = hh;
  *l = __float2half_rn(x - __half2float(hh));
}
__device__ __forceinline__ uint32_t pack_f2h2(float a, float b){
  __half2 t = __floats2half2_rn(a, b);
  return *(uint32_t*)&t;
}

// ---------------- kernel: x + PE -> split fp16 (B,N,C) ---------------------
__global__ void pe_transpose_kernel(const float* __restrict__ x) {
    __shared__ float tile[32][33];
    int b  = blockIdx.z;
    int c0 = blockIdx.y * 32, n0 = blockIdx.x * 32;
    int tx = threadIdx.x, ty = threadIdx.y;
    tile[ty][tx] = x[((size_t)(b*CC + c0 + ty))*NN + n0 + tx];
    __syncthreads();
    int c = c0 + tx, n = n0 + ty;
    int h = n >> 6, w = n & 63;
    int pos, cc;
    if (c < 128) { pos = w; cc = c; } else { pos = h; cc = c - 128; }
    int j = cc & 63;
    float inv = expf(-0.14391156831212787f * (float)j);
    float arg = (float)pos * inv;
    float pe = (cc >= 64) ? cosf(arg) : sinf(arg);
    float v = tile[tx][ty] + pe;
    size_t o = ((size_t)(b*NN + n))*CC + c;
    split2h(v, &g_Xh[o], &g_Xl[o]);
}

// ---------------- kernel: Pt[e,c] = scale * sum_d Wq[d,c]*Wk[d,e] ----------
__global__ void pt_kernel(const float* __restrict__ wq, const float* __restrict__ wk){
  int e = blockIdx.x, c = threadIdx.x;
  float acc = 0.f;
  for (int d = 0; d < CC; d++)
    acc += wq[d*CC + c] * wk[d*CC + e];
  g_Pt[e*CC + c] = __float2half_rn(acc * 0.0625f);
}

__global__ void cvtW_kernel(const float* __restrict__ wv){
  int i = blockIdx.x*256 + threadIdx.x;
  g_Wv[i] = __float2half_rn(wv[i]);
}

// ---------------- mma.sync GEMM (NT), A split hi/lo, B unsplit (2-product) -
// MODE 0: fp16 out row-major (T projection)
// MODE 1: fp16 out transposed (B,C,N) (V projection)
template<int MODE>
__global__ void __launch_bounds__(256, 1)
gemm_mma(const __half* __restrict__ Ah, const __half* __restrict__ Al,
         const __half* __restrict__ Bm, __half* __restrict__ O1,
         int lda, int ldb, int K)
{
  extern __shared__ char sm[];
  const int tid  = threadIdx.x;
  const int lane = tid & 31, wid = tid >> 5;
  const int wm   = (wid >> 2) * 64;
  const int wn   = (wid & 3) * 32;

  const int m0 = blockIdx.y * 128, n0 = blockIdx.x * 128;
  const __half* aH = Ah + (size_t)m0 * lda;
  const __half* aL = Al + (size_t)m0 * lda;
  const __half* bH = Bm + (size_t)n0 * ldb;

  const uint32_t sb = smem_u32(sm);
  // stage: [Ah 16K][Al 16K][B 16K] x2 = 96 KB

  auto load_chunk = [&](int ck, int stage){
    const int kt = ck << 6;
    const uint32_t base = sb + stage * 49152;
    #pragma unroll
    for (int u = 0; u < 4; u++){
      int idx = u*256 + tid;
      int r = idx >> 3, c = idx & 7;
      uint32_t dst = base + r*128 + ((c ^ (r & 7)) << 4);
      size_t g = (size_t)r*lda + kt + c*8;
      cp_async16(dst,         aH + g);
      cp_async16(dst + 16384, aL + g);
    }
    #pragma unroll
    for (int u = 0; u < 4; u++){
      int idx = u*256 + tid;
      int r = idx >> 3, c = idx & 7;
      uint32_t dst = base + 32768 + r*128 + ((c ^ (r & 7)) << 4);
      cp_async16(dst, bH + (size_t)r*ldb + kt + c*8);
    }
    cp_commit();
  };

  float acc[4][4][4] = {};
  const int nchunk = K >> 6;
  load_chunk(0, 0);

  for (int ck = 0; ck < nchunk; ck++){
    const int st = ck & 1;
    if (ck + 1 < nchunk){ load_chunk(ck + 1, st ^ 1); cp_wait1(); }
    else                { cp_wait0(); }
    __syncthreads();

    const uint32_t Abase = sb + st * 49152;
    const uint32_t Bbase = Abase + 32768;
    const int rsel = lane & 15;
    const int csel = lane >> 4;

    #pragma unroll
    for (int ks = 0; ks < 4; ks++){
      const int cA = ks*2 + csel;
      uint32_t ahf[4][4], alf[4][4];
      #pragma unroll
      for (int mt = 0; mt < 4; mt++){
        int row = wm + mt*16 + rsel;
        uint32_t ad = Abase + row*128 + ((cA ^ (row & 7)) << 4);
        ldm4(ahf[mt][0], ahf[mt][1], ahf[mt][2], ahf[mt][3], ad);
        ldm4(alf[mt][0], alf[mt][1], alf[mt][2], alf[mt][3], ad + 16384);
      }
      uint32_t bhf[4][2];
      #pragma unroll
      for (int g = 0; g < 2; g++){
        int row = wn + g*16 + rsel;
        uint32_t bd = Bbase + row*128 + ((cA ^ (row & 7)) << 4);
        uint32_t r0, r1, r2, r3;
        ldm4(r0, r1, r2, r3, bd);
        bhf[g*2][0] = r0; bhf[g*2][1] = r2;
        bhf[g*2+1][0] = r1; bhf[g*2+1][1] = r3;
      }
      #pragma unroll
      for (int mt = 0; mt < 4; mt++)
        #pragma unroll
        for (int nt = 0; nt < 4; nt++){
          mma16816(acc[mt][nt], ahf[mt], bhf[nt]);
          mma16816(acc[mt][nt], alf[mt], bhf[nt]);
        }
    }
    __syncthreads();
  }

  if (MODE == 0){
    #pragma unroll
    for (int mt = 0; mt < 4; mt++)
      #pragma unroll
      for (int nt = 0; nt < 4; nt++){
        int r = m0 + wm + mt*16 + (lane >> 2);
        int c = n0 + wn + nt*8  + (lane & 3)*2;
        *(__half2*)(O1 + (size_t)r*CC + c) =
            __floats2half2_rn(acc[mt][nt][0], acc[mt][nt][1]);
        *(__half2*)(O1 + (size_t)(r+8)*CC + c) =
            __floats2half2_rn(acc[mt][nt][2], acc[mt][nt][3]);
      }
  } else {
    float* stg = (float*)sm;
    #pragma unroll
    for (int mt = 0; mt < 4; mt++)
      #pragma unroll
      for (int nt = 0; nt < 4; nt++){
        int r = wm + mt*16 + (lane >> 2);
        int c = wn + nt*8  + (lane & 3)*2;
        stg[r*132 + c]     = acc[mt][nt][0];
        stg[r*132 + c + 1] = acc[mt][nt][1];
        stg[(r+8)*132 + c]     = acc[mt][nt][2];
        stg[(r+8)*132 + c + 1] = acc[mt][nt][3];
      }
    __syncthreads();
    int b = m0 / NN, tok0 = m0 % NN;
    int cl = tid >> 1, seg = tid & 1;
    size_t base = (size_t)(b*CC + n0 + cl)*NN + tok0 + seg*64;
    #pragma unroll
    for (int i = 0; i < 64; i += 2){
      __half2 hv = __floats2half2_rn(stg[(seg*64 + i)*132 + cl],
                                     stg[(seg*64 + i + 1)*132 + cl]);
      *(__half2*)(O1 + base + i) = hv;
    }
  }
}

// ---------------- fused flash attention, 2-chunk software pipeline ---------
// BQ=128 q/CTA, 8 warps x 16 rows. Loop: softmax_j -> [PV_j || S_{j+1}].
// smem: Q 64K | K ring 2x32K | V ring 2x32K = 192 KB
#define SM_Q    0
#define SM_KR   65536
#define SM_VR   131072
#define SM_FLASH 196608

__global__ void __launch_bounds__(256, 1)
flash_kernel(float* __restrict__ out)
{
  extern __shared__ char sm[];
  const uint32_t sb = smem_u32(sm);
  const int tid = threadIdx.x, lane = tid & 31, wid = tid >> 5;
  const int b  = blockIdx.y;
  const int q0 = blockIdx.x * BQ;
  const int wm = wid * 16;
  const int rsel = lane & 15, csel = lane >> 4;

  auto load_K = [&](int j){
    int k0 = j * BKC;
    uint32_t base = sb + SM_KR + (j & 1)*32768;
    #pragma unroll
    for (int u = 0; u < 8; u++){
      int idx = u*256 + tid;            // 64 rows x 32 chunks
      int r = idx >> 5, c = idx & 31;
      uint32_t dst = base + r*512 + ((c ^ (r & 7)) << 4);
      cp_async16(dst, g_Xh + ((size_t)(b*NN + k0 + r))*CC + c*8);
    }
    cp_commit();
  };
  auto load_V = [&](int j){
    int k0 = j * BKC;
    uint32_t base = sb + SM_VR + (j & 1)*32768;
    #pragma unroll
    for (int u = 0; u < 8; u++){
      int idx = u*256 + tid;            // 256 rows x 8 chunks
      int r = idx >> 3, c = idx & 7;
      uint32_t dst = base + r*128 + ((c ^ (r & 7)) << 4);
      cp_async16(dst, g_Vt + ((size_t)(b*CC + r))*NN + k0 + c*8);
    }
    cp_commit();
  };

  // prologue: [Q], [K0], [V0], [K1]
  #pragma unroll
  for (int u = 0; u < 16; u++){
    int idx = u*256 + tid;              // 128 rows x 32 chunks
    int r = idx >> 5, c = idx & 31;
    uint32_t dst = sb + SM_Q + r*512 + ((c ^ (r & 7)) << 4);
    cp_async16(dst, g_T + ((size_t)(b*NN + q0 + r))*CC + c*8);
  }
  cp_commit();
  load_K(0);
  load_V(0);
  load_K(1);

  float m0r = -1e30f, m1r = -1e30f, l0r = 0.f, l1r = 0.f;
  float accY[32][4] = {};
  float accS[8][4] = {};

  cp_wait2();                 // Q, K0 ready (pending V0, K1)
  __syncthreads();

  // ---- S_0 ----
  {
    const uint32_t Kbase = sb + SM_KR;
    #pragma unroll 4
    for (int ks = 0; ks < 16; ks++){
      const int cA = ks*2 + csel;
      int qrow = wm + rsel;
      uint32_t ad = sb + SM_Q + qrow*512 + ((cA ^ (qrow & 7)) << 4);
      uint32_t qh[4];
      ldm4(qh[0], qh[1], qh[2], qh[3], ad);
      #pragma unroll
      for (int g = 0; g < 4; g++){
        int krow = g*16 + rsel;
        uint32_t bd = Kbase + krow*512 + ((cA ^ (krow & 7)) << 4);
        uint32_t r0, r1, r2, r3;
        ldm4(r0, r1, r2, r3, bd);
        uint32_t be[2] = {r0, r2}, bo[2] = {r1, r3};
        mma16816(accS[2*g],   qh, be);
        mma16816(accS[2*g+1], qh, bo);
      }
    }
  }

  for (int j = 0; j < NCH; j++){
    // ---- softmax_j (from accS) ------------------------------------------
    float mx0 = -1e30f, mx1 = -1e30f;
    #pragma unroll
    for (int nt = 0; nt < 8; nt++){
      mx0 = fmaxf(mx0, fmaxf(accS[nt][0], accS[nt][1]));
      mx1 = fmaxf(mx1, fmaxf(accS[nt][2], accS[nt][3]));
    }
    mx0 = fmaxf(mx0, __shfl_xor_sync(0xffffffffu, mx0, 1));
    mx0 = fmaxf(mx0, __shfl_xor_sync(0xffffffffu, mx0, 2));
    mx1 = fmaxf(mx1, __shfl_xor_sync(0xffffffffu, mx1, 1));
    mx1 = fmaxf(mx1, __shfl_xor_sync(0xffffffffu, mx1, 2));
    float mn0 = fmaxf(m0r, mx0), mn1 = fmaxf(m1r, mx1);
    float f0 = __expf(m0r - mn0), f1 = __expf(m1r - mn1);
    m0r = mn0; m1r = mn1;

    uint32_t pp[8][2];
    float s0 = 0.f, s1 = 0.f;
    #pragma unroll
    for (int nt = 0; nt < 8; nt++){
      float p0 = __expf(accS[nt][0] - mn0);
      float p1 = __expf(accS[nt][1] - mn0);
      float p2 = __expf(accS[nt][2] - mn1);
      float p3 = __expf(accS[nt][3] - mn1);
      s0 += p0 + p1; s1 += p2 + p3;
      pp[nt][0] = pack_f2h2(p0, p1);
      pp[nt][1] = pack_f2h2(p2, p3);
    }
    s0 += __shfl_xor_sync(0xffffffffu, s0, 1);
    s0 += __shfl_xor_sync(0xffffffffu, s0, 2);
    s1 += __shfl_xor_sync(0xffffffffu, s1, 1);
    s1 += __shfl_xor_sync(0xffffffffu, s1, 2);
    l0r = l0r*f0 + s0;
    l1r = l1r*f1 + s1;

    // ---- rescale Y -------------------------------------------------------
    #pragma unroll
    for (int nt = 0; nt < 32; nt++){
      accY[nt][0] *= f0; accY[nt][1] *= f0;
      accY[nt][2] *= f1; accY[nt][3] *= f1;
    }

    // ---- rotate ring -----------------------------------------------------
    __syncthreads();                      // all warps done with K_j, V_{j-1}
    load_V(j + 1 < NCH ? j + 1 : NCH - 1);   // -> vslot (j+1)&1
    load_K(j + 2 < NCH ? j + 2 : NCH - 1);   // -> kslot j&1 (K_j consumed)
    cp_wait2();                           // V_j, K_{j+1} ready
    __syncthreads();

    const uint32_t Vbase = sb + SM_VR + (j & 1)*32768;
    const uint32_t Kbase = sb + SM_KR + ((j + 1) & 1)*32768;
    const bool do_s = (j + 1 < NCH);

    #pragma unroll
    for (int nt = 0; nt < 8; nt++){
      accS[nt][0] = 0.f; accS[nt][1] = 0.f; accS[nt][2] = 0.f; accS[nt][3] = 0.f;
    }

    // ---- interleaved: PV_j + S_{j+1} --------------------------------------
    #pragma unroll
    for (int u = 0; u < 4; u++){
      // PV quarter (K-dim slice kv=u of V)
      {
        uint32_t a_p[4] = {pp[2*u][0], pp[2*u][1], pp[2*u+1][0], pp[2*u+1][1]};
        const int cV = u*2 + csel;
        #pragma unroll
        for (int g = 0; g < 16; g++){
          int vrow = g*16 + rsel;
          uint32_t bd = Vbase + vrow*128 + ((cV ^ (vrow & 7)) << 4);
          uint32_t r0, r1, r2, r3;
          ldm4(r0, r1, r2, r3, bd);
          uint32_t be[2] = {r0, r2}, bo[2] = {r1, r3};
          mma16816(accY[2*g],   a_p, be);
          mma16816(accY[2*g+1], a_p, bo);
        }
      }
      // S quarter (4 k-slices)
      if (do_s){
        #pragma unroll
        for (int s = 0; s < 4; s++){
          const int cA = (u*4 + s)*2 + csel;
          int qrow = wm + rsel;
          uint32_t ad = sb + SM_Q + qrow*512 + ((cA ^ (qrow & 7)) << 4);
          uint32_t qh[4];
          ldm4(qh[0], qh[1], qh[2], qh[3], ad);
          #pragma unroll
          for (int g = 0; g < 4; g++){
            int krow = g*16 + rsel;
            uint32_t bd = Kbase + krow*512 + ((cA ^ (krow & 7)) << 4);
            uint32_t r0, r1, r2, r3;
            ldm4(r0, r1, r2, r3, bd);
            uint32_t be[2] = {r0, r2}, bo[2] = {r1, r3};
            mma16816(accS[2*g],   qh, be);
            mma16816(accS[2*g+1], qh, bo);
          }
        }
      }
    }
  }

  cp_wait0();
  __syncthreads();

  // ---- epilogue: normalize, stage, write (B,C,H,W) -------------------------
  float* stg = (float*)sm;                     // [128 tokens][260]
  {
    float inv0 = 1.0f / l0r, inv1 = 1.0f / l1r;
    int rA = wm + (lane >> 2), rB = rA + 8;
    #pragma unroll
    for (int nt = 0; nt < 32; nt++){
      int c = nt*8 + (lane & 3)*2;
      stg[rA*260 + c]     = accY[nt][0]*inv0;
      stg[rA*260 + c + 1] = accY[nt][1]*inv0;
      stg[rB*260 + c]     = accY[nt][2]*inv1;
      stg[rB*260 + c + 1] = accY[nt][3]*inv1;
    }
  }
  __syncthreads();
  #pragma unroll
  for (int it = 0; it < 4; it++){
    int dim = it*64 + (tid >> 2);
    int seg = (tid & 3) * 32;
    float* op = out + (size_t)(b*CC + dim)*NN + q0 + seg;
    #pragma unroll
    for (int k = 0; k < 32; k += 4){
      float4 v;
      v.x = stg[(seg + k + 0)*260 + dim];
      v.y = stg[(seg + k + 1)*260 + dim];
      v.z = stg[(seg + k + 2)*260 + dim];
      v.w = stg[(seg + k + 3)*260 + dim];
      *(float4*)(op + k) = v;
    }
  }
}

// ---------------- launch ----------------------------------------------------
extern "C" void kernel_launch(void* const* d_in, const int* in_sizes, int n_in,
                              void* d_out, int out_size)
{
    const float* x  = (const float*)d_in[0];
    const float* wq = (const float*)d_in[1];
    const float* wk = (const float*)d_in[2];
    const float* wv = (const float*)d_in[3];
    float* out = (float*)d_out;

    __half *Xh, *Xl, *Pt, *Wv, *T, *Vt;
    cudaGetSymbolAddress((void**)&Xh, g_Xh);  cudaGetSymbolAddress((void**)&Xl, g_Xl);
    cudaGetSymbolAddress((void**)&Pt, g_Pt);  cudaGetSymbolAddress((void**)&Wv, g_Wv);
    cudaGetSymbolAddress((void**)&T,  g_T);   cudaGetSymbolAddress((void**)&Vt, g_Vt);

    const int SMEM_P = 2 * 49152;   // 96 KB
    cudaFuncSetAttribute((const void*)gemm_mma<0>,
        cudaFuncAttributeMaxDynamicSharedMemorySize, SMEM_P);
    cudaFuncSetAttribute((const void*)gemm_mma<1>,
        cudaFuncAttributeMaxDynamicSharedMemorySize, SMEM_P);
    cudaFuncSetAttribute((const void*)flash_kernel,
        cudaFuncAttributeMaxDynamicSharedMemorySize, SM_FLASH);

    // 1) X = x + PE, split fp16, (B,N,C)
    pe_transpose_kernel<<<dim3(NN/32, CC/32, BB), dim3(32,32)>>>(x);

    // 2) Pt = 0.0625 * Wq^T Wk (fp16), Wv fp16
    pt_kernel<<<CC, CC>>>(wq, wk);
    cvtW_kernel<<<CC*CC/256, 256>>>(wv);

    // 3) T = X @ Pt^T -> fp16 row-major (2-product)
    gemm_mma<0><<<dim3(CC/128, MT/128, 1), 256, SMEM_P>>>(
        Xh, Xl, Pt, T, CC, CC, CC);

    // 4) Vt = (X @ Wv^T)^T -> fp16 (B,C,N) (2-product)
    gemm_mma<1><<<dim3(CC/128, MT/128, 1), 256, SMEM_P>>>(
        Xh, Xl, Wv, Vt, CC, CC, CC);

    // 5) fused flash attention -> writes out (B,C,H,W) directly
    flash_kernel<<<dim3(NN/BQ, BB), 256, SM_FLASH>>>(out);
}